// round 1
// baseline (speedup 1.0000x reference)
#include <cuda_runtime.h>
#include <cuda_bf16.h>
#include <math.h>

// Problem constants
#define BB 2
#define CC 64
#define DD 8
#define HH 128
#define WW 128
#define VV (DD*HH*WW)          // 131072
#define LL 101
#define NUM_CONVS 4
#define KD 64
#define NLM 20
#define NN (100 + NLM)         // 120 instance slots
#define EPSV 1e-3f

#define X_ELEMS   (BB*CC*VV)          // 16777216
#define IF_ELEMS  (BB*NN*CC)          // 15360
#define PM_ELEMS  (BB*NN*VV)          // 31457280
#define PK_ELEMS  (BB*NN*KD)          // 15360
#define OUT_FULL  (X_ELEMS + IF_ELEMS + PM_ELEMS + PK_ELEMS)

// ---------------- device scratch (no allocations allowed) ----------------
__device__ float g_bufA[X_ELEMS];
__device__ float g_bufB[X_ELEMS];
__device__ float g_wT[NUM_CONVS*64*9*64];   // [l][ci][tap][co]
__device__ float g_sums[BB*LL*CC];
__device__ float g_counts[BB*LL];
__device__ float g_kraw[BB*NN*KD];
__device__ float g_knorm[BB*NN*KD];
__device__ double g_psum;
__device__ double g_psumsq;

// ---------------- init ----------------
__global__ void init_zero_kernel() {
    int tid = threadIdx.x;
    if (tid == 0) { g_psum = 0.0; g_psumsq = 0.0; }
    for (int i = tid; i < BB*LL*CC; i += 256) g_sums[i] = 0.f;
    for (int i = tid; i < BB*LL; i += 256) g_counts[i] = 0.f;
}

// ---------------- weight transpose: conv_w[l][co][ci][1][ky][kx] -> g_wT[l][ci][tap][co]
__global__ void wtrans_kernel(const float* __restrict__ w) {
    int idx = blockIdx.x * 256 + threadIdx.x;
    if (idx >= NUM_CONVS*64*9*64) return;
    int co = idx & 63;
    int r = idx >> 6;          // (l*64+ci)*9+tap
    int tap = r % 9; r /= 9;
    int ci = r & 63;
    int l = r >> 6;
    g_wT[idx] = w[(size_t)((l*64 + co)*64 + ci)*9 + tap];
}

// ---------------- conv 3x3 (per (b,d) slice), 64->64 ch, bias+ReLU ----------------
#define CI_CHUNK 8

__global__ __launch_bounds__(256, 2)
void conv_kernel(const float* __restrict__ in, float* __restrict__ out,
                 const float* __restrict__ bias, int layer)
{
    __shared__ __align__(16) float sIn[CI_CHUNK][18][19];
    __shared__ __align__(16) float sW[CI_CHUNK][9][64];

    const int bd = blockIdx.z;
    const int b = bd >> 3, d = bd & 7;
    const int h0 = blockIdx.y * 16, w0 = blockIdx.x * 16;
    const int tid = threadIdx.x;
    const int co_grp = tid >> 6;       // 0..3, 16 co each
    const int lane = tid & 63;
    const int row = lane >> 2;         // 0..15
    const int colq = lane & 3;         // 0..3 -> pixels w0+colq*4 .. +3

    float acc[16][4];
    #pragma unroll
    for (int i = 0; i < 16; i++)
        #pragma unroll
        for (int j = 0; j < 4; j++) acc[i][j] = 0.f;

    const float* inb = in + ((size_t)(b*64)*8 + d) * 16384;
    const float* wlay = g_wT + (size_t)layer * 64 * 9 * 64;

    for (int cc = 0; cc < 64; cc += CI_CHUNK) {
        __syncthreads();
        // input tile with halo: CI_CHUNK x 18 x 18
        for (int idx = tid; idx < CI_CHUNK*324; idx += 256) {
            int ci = idx / 324;
            int rem = idx - ci*324;
            int rr = rem / 18, c2 = rem - rr*18;
            int gh = h0 + rr - 1, gw = w0 + c2 - 1;
            float v = 0.f;
            if ((unsigned)gh < 128u && (unsigned)gw < 128u)
                v = inb[(size_t)(cc+ci)*131072 + gh*128 + gw];
            sIn[ci][rr][c2] = v;
        }
        // weights chunk [ci][tap][co] is contiguous in g_wT
        for (int idx = tid; idx < CI_CHUNK*576; idx += 256)
            ((float*)sW)[idx] = wlay[cc*576 + idx];
        __syncthreads();

        #pragma unroll 1
        for (int ci = 0; ci < CI_CHUNK; ci++) {
            float iv[3][6];
            #pragma unroll
            for (int dy = 0; dy < 3; dy++)
                #pragma unroll
                for (int k = 0; k < 6; k++)
                    iv[dy][k] = sIn[ci][row+dy][colq*4 + k];
            #pragma unroll
            for (int dy = 0; dy < 3; dy++)
                #pragma unroll
                for (int dx = 0; dx < 3; dx++) {
                    const float4* wp = (const float4*)&sW[ci][dy*3+dx][co_grp*16];
                    #pragma unroll
                    for (int q = 0; q < 4; q++) {
                        float4 wv = wp[q];
                        #pragma unroll
                        for (int p = 0; p < 4; p++) {
                            float xv = iv[dy][dx+p];
                            acc[q*4+0][p] = fmaf(wv.x, xv, acc[q*4+0][p]);
                            acc[q*4+1][p] = fmaf(wv.y, xv, acc[q*4+1][p]);
                            acc[q*4+2][p] = fmaf(wv.z, xv, acc[q*4+2][p]);
                            acc[q*4+3][p] = fmaf(wv.w, xv, acc[q*4+3][p]);
                        }
                    }
                }
        }
    }

    const int h = h0 + row, wbase = w0 + colq*4;
    #pragma unroll
    for (int i = 0; i < 16; i++) {
        int co = co_grp*16 + i;
        float bv = bias[co];
        float4 o;
        o.x = fmaxf(acc[i][0] + bv, 0.f);
        o.y = fmaxf(acc[i][1] + bv, 0.f);
        o.z = fmaxf(acc[i][2] + bv, 0.f);
        o.w = fmaxf(acc[i][3] + bv, 0.f);
        *(float4*)(out + ((size_t)(b*64+co)*8 + d)*16384 + h*128 + wbase) = o;
    }
}

// ---------------- segment sums (per-label mean pooling) ----------------
#define VCH 2048
__global__ __launch_bounds__(256)
void segsum_kernel(const float* __restrict__ x, const int* __restrict__ labels)
{
    __shared__ float sAcc[LL*CC];
    __shared__ float sCnt[LL];
    __shared__ int sLab[VCH];
    const int b = blockIdx.y;
    const int v0 = blockIdx.x * VCH;
    const int tid = threadIdx.x;

    for (int i = tid; i < LL*CC; i += 256) sAcc[i] = 0.f;
    for (int i = tid; i < LL; i += 256) sCnt[i] = 0.f;
    for (int i = tid; i < VCH; i += 256) sLab[i] = labels[(size_t)b*VV + v0 + i];
    __syncthreads();

    for (int i = tid; i < VCH; i += 256) atomicAdd(&sCnt[sLab[i]], 1.f);
    const float* xb = x + (size_t)b*64*VV + v0;
    for (int c = 0; c < 64; c++) {
        const float* xc = xb + (size_t)c*VV;
        for (int i = tid; i < VCH; i += 256)
            atomicAdd(&sAcc[sLab[i]*64 + c], xc[i]);
    }
    __syncthreads();
    for (int i = tid; i < LL*CC; i += 256) atomicAdd(&g_sums[b*LL*CC + i], sAcc[i]);
    for (int i = tid; i < LL; i += 256) atomicAdd(&g_counts[b*LL + i], sCnt[i]);
}

// ---------------- inst features + mask_kernel linear (raw) ----------------
__global__ __launch_bounds__(256)
void instfeat_kernel(const float* __restrict__ embed, const float* __restrict__ mk_w,
                     const float* __restrict__ mk_b, float* __restrict__ if_out,
                     int write_if)
{
    __shared__ float sInst[NN*CC];     // 30720 B
    __shared__ float sWT[CC*KD];       // transposed [c][kd], 16384 B
    const int b = blockIdx.x;
    const int tid = threadIdx.x;

    for (int idx = tid; idx < CC*KD; idx += 256) {
        int kd = idx & 63, c = idx >> 6;
        sWT[c*64 + kd] = mk_w[kd*64 + c];
    }
    for (int idx = tid; idx < 100*CC; idx += 256) {
        int n = idx >> 6, c = idx & 63;
        int l = n + 1;
        float cnt = fmaxf(g_counts[b*LL + l], 1.f);
        sInst[idx] = g_sums[(b*LL + l)*64 + c] / cnt;
    }
    for (int idx = tid; idx < NLM*CC; idx += 256)
        sInst[100*CC + idx] = embed[idx];
    __syncthreads();

    if (write_if)
        for (int idx = tid; idx < NN*CC; idx += 256)
            if_out[(size_t)b*NN*CC + idx] = sInst[idx];

    for (int idx = tid; idx < NN*KD; idx += 256) {
        int n = idx >> 6, kd = idx & 63;
        const float* ip = sInst + n*64;
        float a = mk_b[kd];
        #pragma unroll
        for (int c = 0; c < 64; c++)
            a = fmaf(ip[c], sWT[c*64 + kd], a);
        g_kraw[(size_t)b*NN*KD + idx] = a;
    }
}

// ---------------- BatchNorm1d over (B,N) per KD channel ----------------
__global__ void bnk_kernel(const float* __restrict__ gamma, const float* __restrict__ beta,
                           float* __restrict__ pk_out, int write_pk)
{
    const int kd = threadIdx.x;  // blockDim = 64
    double s = 0.0, sq = 0.0;
    for (int i = 0; i < BB*NN; i++) {
        float v = g_kraw[i*64 + kd];
        s += (double)v; sq += (double)v * v;
    }
    double mean = s / (double)(BB*NN);
    double var = sq / (double)(BB*NN) - mean*mean;
    float inv = (float)(1.0 / sqrt(var + (double)EPSV));
    float g = gamma[kd], be = beta[kd], m = (float)mean;
    for (int i = 0; i < BB*NN; i++) {
        float v = (g_kraw[i*64 + kd] - m) * inv * g + be;
        g_knorm[i*64 + kd] = v;
        if (write_pk) pk_out[i*64 + kd] = v;
    }
}

// ---------------- bmm: pred_masks = K @ MF, write raw + accumulate stats ----------------
__global__ __launch_bounds__(256)
void bmm_kernel(const float* __restrict__ mf, float* __restrict__ pm)
{
    __shared__ __align__(16) float sK[NN*KD];
    __shared__ float rs[256], rq[256];
    const int b = blockIdx.y;
    const int tid = threadIdx.x;
    const int v = blockIdx.x * 256 + tid;

    for (int i = tid; i < NN*KD; i += 256) sK[i] = g_knorm[b*NN*KD + i];
    __syncthreads();

    float mfv[64];
    const float* mb = mf + (size_t)b*64*VV + v;
    #pragma unroll
    for (int k = 0; k < 64; k++) mfv[k] = mb[(size_t)k*VV];

    float psum = 0.f, psq = 0.f;
    float* po = pm + (size_t)b*NN*VV + v;
    #pragma unroll 4
    for (int n = 0; n < NN; n++) {
        const float4* kp = (const float4*)(sK + n*64);
        float a = 0.f;
        #pragma unroll
        for (int kk = 0; kk < 16; kk++) {
            float4 kv = kp[kk];
            a = fmaf(kv.x, mfv[4*kk+0], a);
            a = fmaf(kv.y, mfv[4*kk+1], a);
            a = fmaf(kv.z, mfv[4*kk+2], a);
            a = fmaf(kv.w, mfv[4*kk+3], a);
        }
        po[(size_t)n*VV] = a;
        psum += a; psq += a*a;
    }
    rs[tid] = psum; rq[tid] = psq;
    __syncthreads();
    for (int s = 128; s > 0; s >>= 1) {
        if (tid < s) { rs[tid] += rs[tid+s]; rq[tid] += rq[tid+s]; }
        __syncthreads();
    }
    if (tid == 0) {
        atomicAdd(&g_psum, (double)rs[0]);
        atomicAdd(&g_psumsq, (double)rq[0]);
    }
}

// ---------------- global BN over pred_masks (in place) ----------------
__global__ void norm_masks_kernel(float* __restrict__ pm,
                                  const float* __restrict__ gam,
                                  const float* __restrict__ bet)
{
    const double N = (double)PM_ELEMS;
    double mean = g_psum / N;
    double var = g_psumsq / N - mean*mean;
    float inv = (float)(1.0 / sqrt(var + (double)EPSV));
    float g = gam[0] * inv;
    float m = (float)mean;
    float be = bet[0];
    float4* p = (float4*)pm;
    const int n4 = PM_ELEMS / 4;
    for (int i = blockIdx.x*blockDim.x + threadIdx.x; i < n4; i += gridDim.x*blockDim.x) {
        float4 v = p[i];
        v.x = (v.x - m)*g + be;
        v.y = (v.y - m)*g + be;
        v.z = (v.z - m)*g + be;
        v.w = (v.w - m)*g + be;
        p[i] = v;
    }
}

// ---------------- launch ----------------
extern "C" void kernel_launch(void* const* d_in, const int* in_sizes, int n_in,
                              void* d_out, int out_size)
{
    const float* features      = (const float*)d_in[0];
    const float* mask_features = (const float*)d_in[1];
    const float* conv_w        = (const float*)d_in[2];
    const float* conv_b        = (const float*)d_in[3];
    const float* embed         = (const float*)d_in[4];
    const float* mk_w          = (const float*)d_in[5];
    const float* mk_b          = (const float*)d_in[6];
    const float* nk_gamma      = (const float*)d_in[7];
    const float* nk_beta       = (const float*)d_in[8];
    const float* nl_gamma      = (const float*)d_in[9];
    const float* nl_beta       = (const float*)d_in[10];
    const int*   init_masks    = (const int*)d_in[11];
    float* out = (float*)d_out;

    float *bufA = nullptr, *bufB = nullptr;
    cudaGetSymbolAddress((void**)&bufA, g_bufA);
    cudaGetSymbolAddress((void**)&bufB, g_bufB);

    // output layout (defensive on out_size)
    int full = (out_size >= OUT_FULL) ? 1 : 0;
    int masks_only = (!full && out_size >= PM_ELEMS) ? 1 : 0;

    float* xout  = full ? out : bufB;                 // final conv result
    float* ifout = full ? (out + X_ELEMS) : out;      // dummy target when not full
    float* pmout = full ? (out + X_ELEMS + IF_ELEMS) : (masks_only ? out : bufB);
    float* pkout = full ? (out + X_ELEMS + IF_ELEMS + PM_ELEMS) : out;

    init_zero_kernel<<<1, 256>>>();
    wtrans_kernel<<<(NUM_CONVS*64*9*64 + 255)/256, 256>>>(conv_w);

    dim3 cgrid(8, 8, BB*DD);
    conv_kernel<<<cgrid, 256>>>(features, bufA, conv_b + 0*64, 0);
    conv_kernel<<<cgrid, 256>>>(bufA, bufB, conv_b + 1*64, 1);
    conv_kernel<<<cgrid, 256>>>(bufB, bufA, conv_b + 2*64, 2);
    conv_kernel<<<cgrid, 256>>>(bufA, xout, conv_b + 3*64, 3);

    segsum_kernel<<<dim3(VV/VCH, BB), 256>>>(xout, init_masks);
    instfeat_kernel<<<BB, 256>>>(embed, mk_w, mk_b, ifout, full);
    bnk_kernel<<<1, 64>>>(nk_gamma, nk_beta, pkout, full);

    if (full || masks_only) {
        bmm_kernel<<<dim3(VV/256, BB), 256>>>(mask_features, pmout);
        norm_masks_kernel<<<4096, 256>>>(pmout, nl_gamma, nl_beta);
    }
}

// round 2
// speedup vs baseline: 1.2112x; 1.2112x over previous
#include <cuda_runtime.h>
#include <cuda_bf16.h>
#include <math.h>

// Problem constants
#define BB 2
#define CC 64
#define DD 8
#define HH 128
#define WW 128
#define VV (DD*HH*WW)          // 131072
#define LL 101
#define NUM_CONVS 4
#define KD 64
#define NLM 20
#define NN (100 + NLM)         // 120 instance slots
#define EPSV 1e-3f

#define X_ELEMS   (BB*CC*VV)          // 16777216
#define IF_ELEMS  (BB*NN*CC)          // 15360
#define PM_ELEMS  (BB*NN*VV)          // 31457280
#define PK_ELEMS  (BB*NN*KD)          // 15360
#define OUT_FULL  (X_ELEMS + IF_ELEMS + PM_ELEMS + PK_ELEMS)

// ---------------- device scratch (no allocations allowed) ----------------
__device__ float g_bufA[X_ELEMS];
__device__ float g_bufB[X_ELEMS];
__device__ float g_wT[NUM_CONVS*64*9*64];   // [l][ci][tap][co]
__device__ float g_sums[BB*LL*CC];
__device__ float g_counts[BB*LL];
__device__ float g_kraw[BB*NN*KD];
__device__ float g_knorm[BB*NN*KD];
__device__ double g_psum;
__device__ double g_psumsq;

// ---------------- packed f32x2 helpers (Blackwell FFMA2) ----------------
typedef unsigned long long u64t;

__device__ __forceinline__ u64t fma2(u64t a, u64t b, u64t c) {
    u64t d;
    asm("fma.rn.f32x2 %0, %1, %2, %3;" : "=l"(d) : "l"(a), "l"(b), "l"(c));
    return d;
}
__device__ __forceinline__ u64t dup2(float v) {
    u64t d;
    asm("mov.b64 %0, {%1, %1};" : "=l"(d) : "f"(v));
    return d;
}
__device__ __forceinline__ u64t pack2(float a, float b) {
    u64t d;
    asm("mov.b64 %0, {%1, %2};" : "=l"(d) : "f"(a), "f"(b));
    return d;
}
__device__ __forceinline__ float2 unpack2(u64t v) {
    float2 r;
    asm("mov.b64 {%0, %1}, %2;" : "=f"(r.x), "=f"(r.y) : "l"(v));
    return r;
}

// ---------------- init ----------------
__global__ void init_zero_kernel() {
    int tid = threadIdx.x;
    if (tid == 0) { g_psum = 0.0; g_psumsq = 0.0; }
    for (int i = tid; i < BB*LL*CC; i += 256) g_sums[i] = 0.f;
    for (int i = tid; i < BB*LL; i += 256) g_counts[i] = 0.f;
}

// ---------------- weight transpose: conv_w[l][co][ci][1][ky][kx] -> g_wT[l][ci][tap][co]
__global__ void wtrans_kernel(const float* __restrict__ w) {
    int idx = blockIdx.x * 256 + threadIdx.x;
    if (idx >= NUM_CONVS*64*9*64) return;
    int co = idx & 63;
    int r = idx >> 6;          // (l*64+ci)*9+tap
    int tap = r % 9; r /= 9;
    int ci = r & 63;
    int l = r >> 6;
    g_wT[idx] = w[(size_t)((l*64 + co)*64 + ci)*9 + tap];
}

// ---------------- conv 3x3 via FFMA2 (per (b,d) slice), 64->64 ch, bias+ReLU --------
// 16x16 spatial tile, 256 threads: co_grp = tid>>5 (8 co per group),
// lane = tid&31: row = lane>>1 (0..15), colh = lane&1 (8-px half).
// Each thread: 8 co (4 f32x2 pairs) x 8 px. Weight pairs loaded directly as u64
// from smem (co-major layout); input values dup'd into both lanes.
#define CI_CHUNK 8

__global__ __launch_bounds__(256, 2)
void conv_kernel(const float* __restrict__ in, float* __restrict__ out,
                 const float* __restrict__ bias, int layer)
{
    __shared__ __align__(16) float sIn[CI_CHUNK][18][20];
    __shared__ __align__(16) float sW[CI_CHUNK][9][64];

    const int bd = blockIdx.z;
    const int b = bd >> 3, d = bd & 7;
    const int h0 = blockIdx.y * 16, w0 = blockIdx.x * 16;
    const int tid = threadIdx.x;
    const int co_grp = tid >> 5;         // 0..7 -> 8 co each
    const int lane = tid & 31;
    const int row = lane >> 1;           // 0..15
    const int colh = lane & 1;           // 0..1
    const int px0 = colh * 8;

    // acc[co_pair][px] with bias folded in
    u64t acc[4][8];
    {
        const int co0 = co_grp * 8;
        #pragma unroll
        for (int cp = 0; cp < 4; cp++) {
            u64t bv = pack2(bias[co0 + 2*cp], bias[co0 + 2*cp + 1]);
            #pragma unroll
            for (int p = 0; p < 8; p++) acc[cp][p] = bv;
        }
    }

    const float* inb = in + ((size_t)(b*64)*8 + d) * 16384;
    const float* wlay = g_wT + (size_t)layer * 64 * 9 * 64;

    for (int cc = 0; cc < 64; cc += CI_CHUNK) {
        __syncthreads();
        // input tile with halo: CI_CHUNK x 18 x 18 (stride 20)
        for (int i = tid; i < CI_CHUNK*324; i += 256) {
            int ci = i / 324;
            int rem = i - ci*324;
            int rr = rem / 18, c2 = rem - rr*18;
            int gh = h0 + rr - 1, gw = w0 + c2 - 1;
            float v = 0.f;
            if ((unsigned)gh < 128u && (unsigned)gw < 128u)
                v = inb[(size_t)(cc+ci)*131072 + gh*128 + gw];
            sIn[ci][rr][c2] = v;
        }
        // weights chunk [ci][tap][co] contiguous in g_wT
        {
            const float4* wsrc = (const float4*)(wlay + cc*576);
            float4* wdst = (float4*)sW;
            #pragma unroll
            for (int j = 0; j < 5; j++) {
                int i = tid + j*256;
                if (i < CI_CHUNK*144) wdst[i] = wsrc[i];
            }
        }
        __syncthreads();

        #pragma unroll 1
        for (int ci = 0; ci < CI_CHUNK; ci++) {
            #pragma unroll
            for (int dy = 0; dy < 3; dy++) {
                const float* rp = &sIn[ci][row + dy][px0];
                float4 va = *(const float4*)rp;
                float4 vb = *(const float4*)(rp + 4);
                float v8 = rp[8], v9 = rp[9];
                u64t dv[10];
                dv[0] = dup2(va.x); dv[1] = dup2(va.y);
                dv[2] = dup2(va.z); dv[3] = dup2(va.w);
                dv[4] = dup2(vb.x); dv[5] = dup2(vb.y);
                dv[6] = dup2(vb.z); dv[7] = dup2(vb.w);
                dv[8] = dup2(v8);   dv[9] = dup2(v9);
                #pragma unroll
                for (int dx = 0; dx < 3; dx++) {
                    const int tap = dy*3 + dx;
                    const ulonglong2* wp =
                        (const ulonglong2*)&sW[ci][tap][co_grp*8];
                    ulonglong2 wA = wp[0];   // pairs (co0,co1),(co2,co3)
                    ulonglong2 wB = wp[1];   // pairs (co4,co5),(co6,co7)
                    #pragma unroll
                    for (int p = 0; p < 8; p++) {
                        u64t iv = dv[p + dx];
                        acc[0][p] = fma2(wA.x, iv, acc[0][p]);
                        acc[1][p] = fma2(wA.y, iv, acc[1][p]);
                        acc[2][p] = fma2(wB.x, iv, acc[2][p]);
                        acc[3][p] = fma2(wB.y, iv, acc[3][p]);
                    }
                }
            }
        }
    }

    // epilogue: unpack, ReLU, store 8 co x 8 px
    const int h = h0 + row, wb = w0 + px0;
    float* ob = out + ((size_t)(b*64)*8 + d) * 16384;
    #pragma unroll
    for (int cp = 0; cp < 4; cp++) {
        const int co = co_grp*8 + cp*2;
        float2 u0 = unpack2(acc[cp][0]);
        float2 u1 = unpack2(acc[cp][1]);
        float2 u2 = unpack2(acc[cp][2]);
        float2 u3 = unpack2(acc[cp][3]);
        float2 u4 = unpack2(acc[cp][4]);
        float2 u5 = unpack2(acc[cp][5]);
        float2 u6 = unpack2(acc[cp][6]);
        float2 u7 = unpack2(acc[cp][7]);
        float4 lo0 = make_float4(fmaxf(u0.x,0.f), fmaxf(u1.x,0.f),
                                 fmaxf(u2.x,0.f), fmaxf(u3.x,0.f));
        float4 lo1 = make_float4(fmaxf(u4.x,0.f), fmaxf(u5.x,0.f),
                                 fmaxf(u6.x,0.f), fmaxf(u7.x,0.f));
        float4 hi0 = make_float4(fmaxf(u0.y,0.f), fmaxf(u1.y,0.f),
                                 fmaxf(u2.y,0.f), fmaxf(u3.y,0.f));
        float4 hi1 = make_float4(fmaxf(u4.y,0.f), fmaxf(u5.y,0.f),
                                 fmaxf(u6.y,0.f), fmaxf(u7.y,0.f));
        float* p0 = ob + (size_t)co*131072 + h*128 + wb;
        float* p1 = p0 + 131072;
        *(float4*)(p0)     = lo0;
        *(float4*)(p0 + 4) = lo1;
        *(float4*)(p1)     = hi0;
        *(float4*)(p1 + 4) = hi1;
    }
}

// ---------------- segment sums (per-label mean pooling) ----------------
#define VCH 2048
__global__ __launch_bounds__(256)
void segsum_kernel(const float* __restrict__ x, const int* __restrict__ labels)
{
    __shared__ float sAcc[LL*CC];
    __shared__ float sCnt[LL];
    __shared__ int sLab[VCH];
    const int b = blockIdx.y;
    const int v0 = blockIdx.x * VCH;
    const int tid = threadIdx.x;

    for (int i = tid; i < LL*CC; i += 256) sAcc[i] = 0.f;
    for (int i = tid; i < LL; i += 256) sCnt[i] = 0.f;
    for (int i = tid; i < VCH; i += 256) sLab[i] = labels[(size_t)b*VV + v0 + i];
    __syncthreads();

    for (int i = tid; i < VCH; i += 256) atomicAdd(&sCnt[sLab[i]], 1.f);
    const float* xb = x + (size_t)b*64*VV + v0;
    for (int c = 0; c < 64; c++) {
        const float* xc = xb + (size_t)c*VV;
        for (int i = tid; i < VCH; i += 256)
            atomicAdd(&sAcc[sLab[i]*64 + c], xc[i]);
    }
    __syncthreads();
    for (int i = tid; i < LL*CC; i += 256) atomicAdd(&g_sums[b*LL*CC + i], sAcc[i]);
    for (int i = tid; i < LL; i += 256) atomicAdd(&g_counts[b*LL + i], sCnt[i]);
}

// ---------------- inst features + mask_kernel linear (raw) ----------------
__global__ __launch_bounds__(256)
void instfeat_kernel(const float* __restrict__ embed, const float* __restrict__ mk_w,
                     const float* __restrict__ mk_b, float* __restrict__ if_out,
                     int write_if)
{
    __shared__ float sInst[NN*CC];     // 30720 B
    __shared__ float sWT[CC*KD];       // transposed [c][kd], 16384 B
    const int b = blockIdx.x;
    const int tid = threadIdx.x;

    for (int idx = tid; idx < CC*KD; idx += 256) {
        int kd = idx & 63, c = idx >> 6;
        sWT[c*64 + kd] = mk_w[kd*64 + c];
    }
    for (int idx = tid; idx < 100*CC; idx += 256) {
        int n = idx >> 6, c = idx & 63;
        int l = n + 1;
        float cnt = fmaxf(g_counts[b*LL + l], 1.f);
        sInst[idx] = g_sums[(b*LL + l)*64 + c] / cnt;
    }
    for (int idx = tid; idx < NLM*CC; idx += 256)
        sInst[100*CC + idx] = embed[idx];
    __syncthreads();

    if (write_if)
        for (int idx = tid; idx < NN*CC; idx += 256)
            if_out[(size_t)b*NN*CC + idx] = sInst[idx];

    for (int idx = tid; idx < NN*KD; idx += 256) {
        int n = idx >> 6, kd = idx & 63;
        const float* ip = sInst + n*64;
        float a = mk_b[kd];
        #pragma unroll
        for (int c = 0; c < 64; c++)
            a = fmaf(ip[c], sWT[c*64 + kd], a);
        g_kraw[(size_t)b*NN*KD + idx] = a;
    }
}

// ---------------- BatchNorm1d over (B,N) per KD channel ----------------
__global__ void bnk_kernel(const float* __restrict__ gamma, const float* __restrict__ beta,
                           float* __restrict__ pk_out, int write_pk)
{
    const int kd = threadIdx.x;  // blockDim = 64
    double s = 0.0, sq = 0.0;
    for (int i = 0; i < BB*NN; i++) {
        float v = g_kraw[i*64 + kd];
        s += (double)v; sq += (double)v * v;
    }
    double mean = s / (double)(BB*NN);
    double var = sq / (double)(BB*NN) - mean*mean;
    float inv = (float)(1.0 / sqrt(var + (double)EPSV));
    float g = gamma[kd], be = beta[kd], m = (float)mean;
    for (int i = 0; i < BB*NN; i++) {
        float v = (g_kraw[i*64 + kd] - m) * inv * g + be;
        g_knorm[i*64 + kd] = v;
        if (write_pk) pk_out[i*64 + kd] = v;
    }
}

// ---------------- bmm: pred_masks = K @ MF, write raw + accumulate stats ----------------
__global__ __launch_bounds__(256)
void bmm_kernel(const float* __restrict__ mf, float* __restrict__ pm)
{
    __shared__ __align__(16) float sK[NN*KD];
    __shared__ float rs[256], rq[256];
    const int b = blockIdx.y;
    const int tid = threadIdx.x;
    const int v = blockIdx.x * 256 + tid;

    for (int i = tid; i < NN*KD; i += 256) sK[i] = g_knorm[b*NN*KD + i];
    __syncthreads();

    float mfv[64];
    const float* mb = mf + (size_t)b*64*VV + v;
    #pragma unroll
    for (int k = 0; k < 64; k++) mfv[k] = mb[(size_t)k*VV];

    float psum = 0.f, psq = 0.f;
    float* po = pm + (size_t)b*NN*VV + v;
    #pragma unroll 4
    for (int n = 0; n < NN; n++) {
        const float4* kp = (const float4*)(sK + n*64);
        float a = 0.f;
        #pragma unroll
        for (int kk = 0; kk < 16; kk++) {
            float4 kv = kp[kk];
            a = fmaf(kv.x, mfv[4*kk+0], a);
            a = fmaf(kv.y, mfv[4*kk+1], a);
            a = fmaf(kv.z, mfv[4*kk+2], a);
            a = fmaf(kv.w, mfv[4*kk+3], a);
        }
        po[(size_t)n*VV] = a;
        psum += a; psq += a*a;
    }
    rs[tid] = psum; rq[tid] = psq;
    __syncthreads();
    for (int s = 128; s > 0; s >>= 1) {
        if (tid < s) { rs[tid] += rs[tid+s]; rq[tid] += rq[tid+s]; }
        __syncthreads();
    }
    if (tid == 0) {
        atomicAdd(&g_psum, (double)rs[0]);
        atomicAdd(&g_psumsq, (double)rq[0]);
    }
}

// ---------------- global BN over pred_masks (in place) ----------------
__global__ void norm_masks_kernel(float* __restrict__ pm,
                                  const float* __restrict__ gam,
                                  const float* __restrict__ bet)
{
    const double N = (double)PM_ELEMS;
    double mean = g_psum / N;
    double var = g_psumsq / N - mean*mean;
    float inv = (float)(1.0 / sqrt(var + (double)EPSV));
    float g = gam[0] * inv;
    float m = (float)mean;
    float be = bet[0];
    float4* p = (float4*)pm;
    const int n4 = PM_ELEMS / 4;
    for (int i = blockIdx.x*blockDim.x + threadIdx.x; i < n4; i += gridDim.x*blockDim.x) {
        float4 v = p[i];
        v.x = (v.x - m)*g + be;
        v.y = (v.y - m)*g + be;
        v.z = (v.z - m)*g + be;
        v.w = (v.w - m)*g + be;
        p[i] = v;
    }
}

// ---------------- launch ----------------
extern "C" void kernel_launch(void* const* d_in, const int* in_sizes, int n_in,
                              void* d_out, int out_size)
{
    const float* features      = (const float*)d_in[0];
    const float* mask_features = (const float*)d_in[1];
    const float* conv_w        = (const float*)d_in[2];
    const float* conv_b        = (const float*)d_in[3];
    const float* embed         = (const float*)d_in[4];
    const float* mk_w          = (const float*)d_in[5];
    const float* mk_b          = (const float*)d_in[6];
    const float* nk_gamma      = (const float*)d_in[7];
    const float* nk_beta       = (const float*)d_in[8];
    const float* nl_gamma      = (const float*)d_in[9];
    const float* nl_beta       = (const float*)d_in[10];
    const int*   init_masks    = (const int*)d_in[11];
    float* out = (float*)d_out;

    float *bufA = nullptr, *bufB = nullptr;
    cudaGetSymbolAddress((void**)&bufA, g_bufA);
    cudaGetSymbolAddress((void**)&bufB, g_bufB);

    // output layout (defensive on out_size)
    int full = (out_size >= OUT_FULL) ? 1 : 0;
    int masks_only = (!full && out_size >= PM_ELEMS) ? 1 : 0;

    float* xout  = full ? out : bufB;                 // final conv result
    float* ifout = full ? (out + X_ELEMS) : out;      // dummy target when not full
    float* pmout = full ? (out + X_ELEMS + IF_ELEMS) : (masks_only ? out : bufB);
    float* pkout = full ? (out + X_ELEMS + IF_ELEMS + PM_ELEMS) : out;

    init_zero_kernel<<<1, 256>>>();
    wtrans_kernel<<<(NUM_CONVS*64*9*64 + 255)/256, 256>>>(conv_w);

    dim3 cgrid(8, 8, BB*DD);
    conv_kernel<<<cgrid, 256>>>(features, bufA, conv_b + 0*64, 0);
    conv_kernel<<<cgrid, 256>>>(bufA, bufB, conv_b + 1*64, 1);
    conv_kernel<<<cgrid, 256>>>(bufB, bufA, conv_b + 2*64, 2);
    conv_kernel<<<cgrid, 256>>>(bufA, xout, conv_b + 3*64, 3);

    segsum_kernel<<<dim3(VV/VCH, BB), 256>>>(xout, init_masks);
    instfeat_kernel<<<BB, 256>>>(embed, mk_w, mk_b, ifout, full);
    bnk_kernel<<<1, 64>>>(nk_gamma, nk_beta, pkout, full);

    if (full || masks_only) {
        bmm_kernel<<<dim3(VV/256, BB), 256>>>(mask_features, pmout);
        norm_masks_kernel<<<4096, 256>>>(pmout, nl_gamma, nl_beta);
    }
}

// round 5
// speedup vs baseline: 1.3366x; 1.1035x over previous
#include <cuda_runtime.h>
#include <cuda_bf16.h>
#include <math.h>
#include <stdint.h>

// Problem constants
#define BB 2
#define CC 64
#define DD 8
#define HH 128
#define WW 128
#define VV (DD*HH*WW)          // 131072
#define LL 101
#define KD 64
#define NLM 20
#define NN (100 + NLM)         // 120
#define EPSV 1e-3f

#define X_ELEMS   (BB*CC*VV)          // 16777216
#define IF_ELEMS  (BB*NN*CC)
#define PM_ELEMS  (BB*NN*VV)
#define PK_ELEMS  (BB*NN*KD)
#define OUT_FULL  (X_ELEMS + IF_ELEMS + PM_ELEMS + PK_ELEMS)

#define HALF_ELEMS 16777216           // bf16 elems per (hi|lo) half of a scratch buffer

// ---------------- device scratch ----------------
__device__ float g_bufA[X_ELEMS];     // 64 MB: holds Hi bf16 [0..16M) + Lo bf16 [16M..32M)
__device__ float g_bufB[X_ELEMS];
__device__ float g_sums[BB*LL*CC];
__device__ float g_counts[BB*LL];
__device__ float g_kraw[BB*NN*KD];
__device__ float g_knorm[BB*NN*KD];
__device__ double g_psum;
__device__ double g_psumsq;

// ================= helpers =================
__device__ __forceinline__ uint32_t smem_u32(const void* p) {
    uint32_t a;
    asm("{ .reg .u64 t; cvta.to.shared.u64 t, %1; cvt.u32.u64 %0, t; }"
        : "=r"(a) : "l"(p));
    return a;
}
__device__ __forceinline__ uint32_t pack_bits(__nv_bfloat16 lo, __nv_bfloat16 hi) {
    return (uint32_t)__bfloat16_as_ushort(lo) | ((uint32_t)__bfloat16_as_ushort(hi) << 16);
}
__device__ __forceinline__ uint32_t pack_cvt(float lo, float hi) {
    uint32_t r;
    asm("cvt.rn.bf16x2.f32 %0, %1, %2;" : "=r"(r) : "f"(hi), "f"(lo));
    return r;
}

#define LDSM4(r0,r1,r2,r3, addr) \
    asm volatile("ldmatrix.sync.aligned.m8n8.x4.shared.b16 {%0,%1,%2,%3}, [%4];" \
        : "=r"(r0),"=r"(r1),"=r"(r2),"=r"(r3) : "r"(addr))

#define MMA16816(d, a0,a1,a2,a3, b0,b1) \
    asm volatile("mma.sync.aligned.m16n8k16.row.col.f32.bf16.bf16.f32 " \
        "{%0,%1,%2,%3}, {%4,%5,%6,%7}, {%8,%9}, {%0,%1,%2,%3};" \
        : "+f"((d)[0]), "+f"((d)[1]), "+f"((d)[2]), "+f"((d)[3]) \
        : "r"(a0),"r"(a1),"r"(a2),"r"(a3), "r"(b0),"r"(b1))

// ---------------- init ----------------
__global__ void init_zero_kernel() {
    int tid = threadIdx.x;
    if (tid == 0) { g_psum = 0.0; g_psumsq = 0.0; }
    for (int i = tid; i < BB*LL*CC; i += 256) g_sums[i] = 0.f;
    for (int i = tid; i < BB*LL; i += 256) g_counts[i] = 0.f;
}

// ---------------- features (ch-major fp32) -> pixel-major bf16 hi/lo ----------------
__global__ __launch_bounds__(256)
void trans_kernel(const float* __restrict__ in, uint16_t* __restrict__ outHi) {
    __shared__ float s[64][129];
    const int blk = blockIdx.x;
    const int sl = blk >> 7;
    const int h  = blk & 127;
    const int b = sl >> 3, d = sl & 7;
    const int tid = threadIdx.x;
    for (int i = tid; i < 8192; i += 256) {
        int c = i >> 7, w = i & 127;
        s[c][w] = in[((size_t)(b*64 + c)*8 + d)*16384 + h*128 + w];
    }
    __syncthreads();
    for (int i = tid; i < 1024; i += 256) {
        int w = i >> 3, ch = i & 7;
        uint32_t hw[4], lw[4];
        #pragma unroll
        for (int j = 0; j < 4; j++) {
            float v0 = s[ch*8 + 2*j][w];
            float v1 = s[ch*8 + 2*j + 1][w];
            __nv_bfloat16 h0 = __float2bfloat16(v0);
            __nv_bfloat16 h1 = __float2bfloat16(v1);
            hw[j] = pack_bits(h0, h1);
            lw[j] = pack_cvt(v0 - __bfloat162float(h0), v1 - __bfloat162float(h1));
        }
        size_t e = (((size_t)sl*128 + h)*128 + w)*64 + ch*8;
        *(uint4*)(outHi + e) = make_uint4(hw[0], hw[1], hw[2], hw[3]);
        *(uint4*)(outHi + HALF_ELEMS + e) = make_uint4(lw[0], lw[1], lw[2], lw[3]);
    }
}

// ================= mma.sync conv =================
// Tile: 64 output px (half h-row) x 64 co. GEMM M=64(co) N=64(px)
// K = 3 splits x 9 taps x 64 ci. Split passes: (Whi,Xhi),(Whi,Xlo),(Wlo,Xhi).
// smem layout (dynamic):
#define SM_W_HI  0
#define SM_W_LO  73728
#define SM_IN_HI 147456
#define SM_IN_LO 172800
#define SM_S     198144
#define SM_BIAS  214784
#define CONV_SMEM 215040
#define IN_ROW   8448          // 66 px * 128 B
#define GRIDC 148

__global__ __launch_bounds__(256, 1)
void conv_mma_kernel(const uint16_t* __restrict__ inBuf,   // Hi, Lo at +HALF_ELEMS
                     void* __restrict__ outP,
                     const float* __restrict__ wsrc,       // [co][ci][9] this layer
                     const float* __restrict__ bias,
                     int mode)                             // 0: bf16 hi/lo px-major, 1: fp32 ch-major
{
    extern __shared__ char smem[];
    const uint32_t sb = smem_u32(smem);
    float* S = (float*)(smem + SM_S);
    float* sBias = (float*)(smem + SM_BIAS);
    const int tid = threadIdx.x;
    const int wid = tid >> 5, lane = tid & 31;

    // ---- weights -> smem (hi & lo, swizzled rows of 128B) ----
    for (int i = tid; i < 18432; i += 256) {
        int tap = i >> 11; int r2 = i & 2047;
        int co = r2 >> 5; int cp = r2 & 31; int ci = cp*2;
        float wa = wsrc[(co*64 + ci)*9 + tap];
        float wb = wsrc[(co*64 + ci + 1)*9 + tap];
        __nv_bfloat16 ha = __float2bfloat16(wa);
        __nv_bfloat16 hb = __float2bfloat16(wb);
        uint32_t hi = pack_bits(ha, hb);
        uint32_t lo = pack_cvt(wa - __bfloat162float(ha), wb - __bfloat162float(hb));
        uint32_t off = (uint32_t)(co*128 + cp*4);
        uint32_t sw = off ^ ((off >> 3) & 0x70);
        *(uint32_t*)(smem + SM_W_HI + tap*8192 + sw) = hi;
        *(uint32_t*)(smem + SM_W_LO + tap*8192 + sw) = lo;
    }
    if (tid < 64) sBias[tid] = bias[tid];
    __syncthreads();

    // warp tiling: 4 warps along co (16 each), 2 along px (32 each)
    const int co_base = (wid & 3) * 16;
    const int px_base = (wid >> 2) * 32;
    // ldmatrix lane address roles
    const int am  = (lane & 7) + ((lane >> 3) & 1) * 8;   // A row (m)
    const int akh = lane >> 4;                            // A k-half
    const int bn  = (lane & 7) + (lane >> 4) * 8;         // B row (n)
    const int bkh = (lane >> 3) & 1;                      // B k-half
    const uint32_t axor = (uint32_t)((am & 7) << 4);

    for (int t = blockIdx.x; t < 4096; t += GRIDC) {
        const int sl = t >> 8;
        const int h  = (t >> 1) & 127;
        const int w0 = (t & 1) << 6;

        // ---- stage 3 input rows x 66 px (hi & lo), swizzled ----
        for (int i = tid; i < 3168; i += 256) {
            int bsel = (i >= 1584) ? 1 : 0;
            int r = i - bsel*1584;
            int ky = r / 528; int rem = r - ky*528;
            int px = rem >> 3; int ch = rem & 7;
            int gh = h + ky - 1, gw = w0 - 1 + px;
            uint4 v = make_uint4(0,0,0,0);
            if ((unsigned)gh < 128u && (unsigned)gw < 128u)
                v = *(const uint4*)(inBuf + (size_t)bsel*HALF_ELEMS +
                        (((size_t)sl*128 + gh)*128 + gw)*64 + ch*8);
            *(uint4*)(smem + SM_IN_HI + bsel*25344 + ky*IN_ROW +
                      px*128 + ((ch ^ (px & 7)) << 4)) = v;
        }
        __syncthreads();

        float acc[4][4] = {};
        #pragma unroll 1
        for (int sp = 0; sp < 3; sp++) {
            const uint32_t aB = sb + (sp == 2 ? SM_W_LO : SM_W_HI);
            const uint32_t bB = sb + (sp == 1 ? SM_IN_LO : SM_IN_HI);
            #pragma unroll 1
            for (int ky = 0; ky < 3; ky++) {
                const uint32_t bRow = bB + ky*IN_ROW;
                #pragma unroll
                for (int kx = 0; kx < 3; kx++) {
                    const uint32_t aT = aB + (ky*3 + kx)*8192;
                    const int spx1 = px_base + bn + kx;
                    const int spx2 = spx1 + 16;
                    const uint32_t bx1 = (uint32_t)((spx1 & 7) << 4);
                    const uint32_t bx2 = (uint32_t)((spx2 & 7) << 4);
                    #pragma unroll
                    for (int kc = 0; kc < 4; kc++) {
                        const uint32_t ku = (uint32_t)(kc*32 + akh*16);
                        const uint32_t kub = (uint32_t)(kc*32 + bkh*16);
                        uint32_t a0,a1,a2,a3;
                        LDSM4(a0,a1,a2,a3,
                              aT + (uint32_t)((co_base + am)*128) + (ku ^ axor));
                        uint32_t r0,r1,r2,r3, r4,r5,r6,r7;
                        LDSM4(r0,r1,r2,r3,
                              bRow + (uint32_t)(spx1*128) + (kub ^ bx1));
                        LDSM4(r4,r5,r6,r7,
                              bRow + (uint32_t)(spx2*128) + (kub ^ bx2));
                        MMA16816(acc[0], a0,a1,a2,a3, r0,r1);
                        MMA16816(acc[1], a0,a1,a2,a3, r2,r3);
                        MMA16816(acc[2], a0,a1,a2,a3, r4,r5);
                        MMA16816(acc[3], a0,a1,a2,a3, r6,r7);
                    }
                }
            }
        }

        // ---- fragments -> S[px][co] ----
        #pragma unroll
        for (int j = 0; j < 4; j++) {
            int pc = px_base + 8*j + 2*(lane & 3);
            int mr = co_base + (lane >> 2);
            S[pc*65 + mr]           = acc[j][0];
            S[(pc+1)*65 + mr]       = acc[j][1];
            S[pc*65 + mr + 8]       = acc[j][2];
            S[(pc+1)*65 + mr + 8]   = acc[j][3];
        }
        __syncthreads();

        // ---- epilogue ----
        if (mode == 0) {
            const int px = tid >> 2, cb = (tid & 3) * 16;
            uint32_t hw[8], lw[8];
            #pragma unroll
            for (int j = 0; j < 8; j++) {
                float v0 = fmaxf(S[px*65 + cb + 2*j]     + sBias[cb + 2*j],     0.f);
                float v1 = fmaxf(S[px*65 + cb + 2*j + 1] + sBias[cb + 2*j + 1], 0.f);
                __nv_bfloat16 h0 = __float2bfloat16(v0);
                __nv_bfloat16 h1 = __float2bfloat16(v1);
                hw[j] = pack_bits(h0, h1);
                lw[j] = pack_cvt(v0 - __bfloat162float(h0), v1 - __bfloat162float(h1));
            }
            uint16_t* ob = (uint16_t*)outP;
            size_t e = (((size_t)sl*128 + h)*128 + (w0 + px))*64 + cb;
            *(uint4*)(ob + e)     = make_uint4(hw[0], hw[1], hw[2], hw[3]);
            *(uint4*)(ob + e + 8) = make_uint4(hw[4], hw[5], hw[6], hw[7]);
            *(uint4*)(ob + HALF_ELEMS + e)     = make_uint4(lw[0], lw[1], lw[2], lw[3]);
            *(uint4*)(ob + HALF_ELEMS + e + 8) = make_uint4(lw[4], lw[5], lw[6], lw[7]);
        } else {
            const int co = tid >> 2, pb = (tid & 3) * 16;
            const int b_ = sl >> 3, d_ = sl & 7;
            const float bv = sBias[co];
            float* ob = (float*)outP +
                ((size_t)(b_*64 + co)*8 + d_)*16384 + h*128 + w0 + pb;
            #pragma unroll
            for (int q = 0; q < 4; q++) {
                float4 o;
                o.x = fmaxf(S[(pb + 4*q + 0)*65 + co] + bv, 0.f);
                o.y = fmaxf(S[(pb + 4*q + 1)*65 + co] + bv, 0.f);
                o.z = fmaxf(S[(pb + 4*q + 2)*65 + co] + bv, 0.f);
                o.w = fmaxf(S[(pb + 4*q + 3)*65 + co] + bv, 0.f);
                *(float4*)(ob + 4*q) = o;
            }
        }
        __syncthreads();
    }
}

// ---------------- segment sums ----------------
#define VCH 2048
__global__ __launch_bounds__(256)
void segsum_kernel(const float* __restrict__ x, const int* __restrict__ labels)
{
    __shared__ float sAcc[LL*CC];
    __shared__ float sCnt[LL];
    __shared__ int sLab[VCH];
    const int b = blockIdx.y;
    const int v0 = blockIdx.x * VCH;
    const int tid = threadIdx.x;

    for (int i = tid; i < LL*CC; i += 256) sAcc[i] = 0.f;
    for (int i = tid; i < LL; i += 256) sCnt[i] = 0.f;
    for (int i = tid; i < VCH; i += 256) sLab[i] = labels[(size_t)b*VV + v0 + i];
    __syncthreads();

    for (int i = tid; i < VCH; i += 256) atomicAdd(&sCnt[sLab[i]], 1.f);
    const float* xb = x + (size_t)b*64*VV + v0;
    for (int c = 0; c < 64; c++) {
        const float* xc = xb + (size_t)c*VV;
        for (int i = tid; i < VCH; i += 256)
            atomicAdd(&sAcc[sLab[i]*64 + c], xc[i]);
    }
    __syncthreads();
    for (int i = tid; i < LL*CC; i += 256) atomicAdd(&g_sums[b*LL*CC + i], sAcc[i]);
    for (int i = tid; i < LL; i += 256) atomicAdd(&g_counts[b*LL + i], sCnt[i]);
}

// ---------------- inst features + mask_kernel linear ----------------
__global__ __launch_bounds__(256)
void instfeat_kernel(const float* __restrict__ embed, const float* __restrict__ mk_w,
                     const float* __restrict__ mk_b, float* __restrict__ if_out,
                     int write_if)
{
    __shared__ float sInst[NN*CC];
    __shared__ float sWT[CC*KD];
    const int b = blockIdx.x;
    const int tid = threadIdx.x;

    for (int idx = tid; idx < CC*KD; idx += 256) {
        int kd = idx & 63, c = idx >> 6;
        sWT[c*64 + kd] = mk_w[kd*64 + c];
    }
    for (int idx = tid; idx < 100*CC; idx += 256) {
        int n = idx >> 6, c = idx & 63;
        int l = n + 1;
        float cnt = fmaxf(g_counts[b*LL + l], 1.f);
        sInst[idx] = g_sums[(b*LL + l)*64 + c] / cnt;
    }
    for (int idx = tid; idx < NLM*CC; idx += 256)
        sInst[100*CC + idx] = embed[idx];
    __syncthreads();

    if (write_if)
        for (int idx = tid; idx < NN*CC; idx += 256)
            if_out[(size_t)b*NN*CC + idx] = sInst[idx];

    for (int idx = tid; idx < NN*KD; idx += 256) {
        int n = idx >> 6, kd = idx & 63;
        const float* ip = sInst + n*64;
        float a = mk_b[kd];
        #pragma unroll
        for (int c = 0; c < 64; c++)
            a = fmaf(ip[c], sWT[c*64 + kd], a);
        g_kraw[(size_t)b*NN*KD + idx] = a;
    }
}

// ---------------- BatchNorm1d over (B,N) per KD channel ----------------
__global__ void bnk_kernel(const float* __restrict__ gamma, const float* __restrict__ beta,
                           float* __restrict__ pk_out, int write_pk)
{
    const int kd = threadIdx.x;
    double s = 0.0, sq = 0.0;
    for (int i = 0; i < BB*NN; i++) {
        float v = g_kraw[i*64 + kd];
        s += (double)v; sq += (double)v * v;
    }
    double mean = s / (double)(BB*NN);
    double var = sq / (double)(BB*NN) - mean*mean;
    float inv = (float)(1.0 / sqrt(var + (double)EPSV));
    float g = gamma[kd], be = beta[kd], m = (float)mean;
    for (int i = 0; i < BB*NN; i++) {
        float v = (g_kraw[i*64 + kd] - m) * inv * g + be;
        g_knorm[i*64 + kd] = v;
        if (write_pk) pk_out[i*64 + kd] = v;
    }
}

// ---------------- bmm + stats ----------------
__global__ __launch_bounds__(256)
void bmm_kernel(const float* __restrict__ mf, float* __restrict__ pm)
{
    __shared__ __align__(16) float sK[NN*KD];
    __shared__ float rs[256], rq[256];
    const int b = blockIdx.y;
    const int tid = threadIdx.x;
    const int v = blockIdx.x * 256 + tid;

    for (int i = tid; i < NN*KD; i += 256) sK[i] = g_knorm[b*NN*KD + i];
    __syncthreads();

    float mfv[64];
    const float* mb = mf + (size_t)b*64*VV + v;
    #pragma unroll
    for (int k = 0; k < 64; k++) mfv[k] = mb[(size_t)k*VV];

    float psum = 0.f, psq = 0.f;
    float* po = pm + (size_t)b*NN*VV + v;
    #pragma unroll 4
    for (int n = 0; n < NN; n++) {
        const float4* kp = (const float4*)(sK + n*64);
        float a = 0.f;
        #pragma unroll
        for (int kk = 0; kk < 16; kk++) {
            float4 kv = kp[kk];
            a = fmaf(kv.x, mfv[4*kk+0], a);
            a = fmaf(kv.y, mfv[4*kk+1], a);
            a = fmaf(kv.z, mfv[4*kk+2], a);
            a = fmaf(kv.w, mfv[4*kk+3], a);
        }
        po[(size_t)n*VV] = a;
        psum += a; psq += a*a;
    }
    rs[tid] = psum; rq[tid] = psq;
    __syncthreads();
    for (int s = 128; s > 0; s >>= 1) {
        if (tid < s) { rs[tid] += rs[tid+s]; rq[tid] += rq[tid+s]; }
        __syncthreads();
    }
    if (tid == 0) {
        atomicAdd(&g_psum, (double)rs[0]);
        atomicAdd(&g_psumsq, (double)rq[0]);
    }
}

// ---------------- global BN over pred_masks ----------------
__global__ void norm_masks_kernel(float* __restrict__ pm,
                                  const float* __restrict__ gam,
                                  const float* __restrict__ bet)
{
    const double N = (double)PM_ELEMS;
    double mean = g_psum / N;
    double var = g_psumsq / N - mean*mean;
    float inv = (float)(1.0 / sqrt(var + (double)EPSV));
    float g = gam[0] * inv;
    float m = (float)mean;
    float be = bet[0];
    float4* p = (float4*)pm;
    const int n4 = PM_ELEMS / 4;
    for (int i = blockIdx.x*blockDim.x + threadIdx.x; i < n4; i += gridDim.x*blockDim.x) {
        float4 v = p[i];
        v.x = (v.x - m)*g + be;
        v.y = (v.y - m)*g + be;
        v.z = (v.z - m)*g + be;
        v.w = (v.w - m)*g + be;
        p[i] = v;
    }
}

// ---------------- launch ----------------
extern "C" void kernel_launch(void* const* d_in, const int* in_sizes, int n_in,
                              void* d_out, int out_size)
{
    const float* features      = (const float*)d_in[0];
    const float* mask_features = (const float*)d_in[1];
    const float* conv_w        = (const float*)d_in[2];
    const float* conv_b        = (const float*)d_in[3];
    const float* embed         = (const float*)d_in[4];
    const float* mk_w          = (const float*)d_in[5];
    const float* mk_b          = (const float*)d_in[6];
    const float* nk_gamma      = (const float*)d_in[7];
    const float* nk_beta       = (const float*)d_in[8];
    const float* nl_gamma      = (const float*)d_in[9];
    const float* nl_beta       = (const float*)d_in[10];
    const int*   init_masks    = (const int*)d_in[11];
    float* out = (float*)d_out;

    float *bufA = nullptr, *bufB = nullptr;
    cudaGetSymbolAddress((void**)&bufA, g_bufA);
    cudaGetSymbolAddress((void**)&bufB, g_bufB);
    uint16_t* hA = (uint16_t*)bufA;
    uint16_t* hB = (uint16_t*)bufB;

    int full = (out_size >= OUT_FULL) ? 1 : 0;
    int masks_only = (!full && out_size >= PM_ELEMS) ? 1 : 0;

    float* xout  = full ? out : bufB;
    float* ifout = full ? (out + X_ELEMS) : out;
    float* pmout = full ? (out + X_ELEMS + IF_ELEMS) : (masks_only ? out : bufB);
    float* pkout = full ? (out + X_ELEMS + IF_ELEMS + PM_ELEMS) : out;

    static int attr_done = 0;
    if (!attr_done) {
        cudaFuncSetAttribute(conv_mma_kernel,
                             cudaFuncAttributeMaxDynamicSharedMemorySize, CONV_SMEM);
        attr_done = 1;
    }

    init_zero_kernel<<<1, 256>>>();
    trans_kernel<<<2048, 256>>>(features, hB);

    conv_mma_kernel<<<GRIDC, 256, CONV_SMEM>>>(hB, hA,   conv_w + 0*36864, conv_b + 0,   0);
    conv_mma_kernel<<<GRIDC, 256, CONV_SMEM>>>(hA, hB,   conv_w + 1*36864, conv_b + 64,  0);
    conv_mma_kernel<<<GRIDC, 256, CONV_SMEM>>>(hB, hA,   conv_w + 2*36864, conv_b + 128, 0);
    conv_mma_kernel<<<GRIDC, 256, CONV_SMEM>>>(hA, xout, conv_w + 3*36864, conv_b + 192, 1);

    segsum_kernel<<<dim3(VV/VCH, BB), 256>>>(xout, init_masks);
    instfeat_kernel<<<BB, 256>>>(embed, mk_w, mk_b, ifout, full);
    bnk_kernel<<<1, 64>>>(nk_gamma, nk_beta, pkout, full);

    if (full || masks_only) {
        bmm_kernel<<<dim3(VV/256, BB), 256>>>(mask_features, pmout);
        norm_masks_kernel<<<4096, 256>>>(pmout, nl_gamma, nl_beta);
    }
}

// round 6
// speedup vs baseline: 1.7680x; 1.3227x over previous
#include <cuda_runtime.h>
#include <cuda_bf16.h>
#include <math.h>
#include <stdint.h>

// Problem constants
#define BB 2
#define CC 64
#define DD 8
#define HH 128
#define WW 128
#define VV (DD*HH*WW)          // 131072
#define LL 101
#define KD 64
#define NLM 20
#define NN (100 + NLM)         // 120
#define EPSV 1e-3f

#define X_ELEMS   (BB*CC*VV)          // 16777216
#define IF_ELEMS  (BB*NN*CC)
#define PM_ELEMS  (BB*NN*VV)
#define PK_ELEMS  (BB*NN*KD)
#define OUT_FULL  (X_ELEMS + IF_ELEMS + PM_ELEMS + PK_ELEMS)

#define HALF_ELEMS 16777216           // bf16 elems per (hi|lo) half of a scratch buffer

// ---------------- device scratch ----------------
__device__ float g_bufA[X_ELEMS];     // 64 MB: Hi bf16 [0..16M) + Lo bf16 [16M..32M)
__device__ float g_bufB[X_ELEMS];
__device__ uint4 g_wfragLo[4*9*4*4*32];   // Wlo in mma-A fragment order, per layer 4608 uint4
__device__ float g_sums[BB*LL*CC];
__device__ float g_counts[BB*LL];
__device__ float g_kraw[BB*NN*KD];
__device__ float g_knorm[BB*NN*KD];
__device__ double g_psum;
__device__ double g_psumsq;

// ================= helpers =================
__device__ __forceinline__ uint32_t smem_u32(const void* p) {
    uint32_t a;
    asm("{ .reg .u64 t; cvta.to.shared.u64 t, %1; cvt.u32.u64 %0, t; }"
        : "=r"(a) : "l"(p));
    return a;
}
__device__ __forceinline__ uint32_t pack_bits(__nv_bfloat16 lo, __nv_bfloat16 hi) {
    return (uint32_t)__bfloat16_as_ushort(lo) | ((uint32_t)__bfloat16_as_ushort(hi) << 16);
}
__device__ __forceinline__ uint32_t pack_cvt(float lo, float hi) {
    uint32_t r;
    asm("cvt.rn.bf16x2.f32 %0, %1, %2;" : "=r"(r) : "f"(hi), "f"(lo));
    return r;
}
__device__ __forceinline__ float bf_round(float x) {
    return __bfloat162float(__float2bfloat16(x));
}

#define LDSM4(r0,r1,r2,r3, addr) \
    asm volatile("ldmatrix.sync.aligned.m8n8.x4.shared.b16 {%0,%1,%2,%3}, [%4];" \
        : "=r"(r0),"=r"(r1),"=r"(r2),"=r"(r3) : "r"(addr))

#define MMA16816(d, a0,a1,a2,a3, b0,b1) \
    asm volatile("mma.sync.aligned.m16n8k16.row.col.f32.bf16.bf16.f32 " \
        "{%0,%1,%2,%3}, {%4,%5,%6,%7}, {%8,%9}, {%0,%1,%2,%3};" \
        : "+f"((d)[0]), "+f"((d)[1]), "+f"((d)[2]), "+f"((d)[3]) \
        : "r"(a0),"r"(a1),"r"(a2),"r"(a3), "r"(b0),"r"(b1))

#define CP_ASYNC16(dst, src, n) \
    asm volatile("cp.async.cg.shared.global [%0], [%1], 16, %2;" \
        :: "r"(dst), "l"(src), "r"(n) : "memory")
#define CP_COMMIT() asm volatile("cp.async.commit_group;" ::: "memory")
#define CP_WAIT0()  asm volatile("cp.async.wait_group 0;" ::: "memory")
#define CP_WAIT1()  asm volatile("cp.async.wait_group 1;" ::: "memory")

// ---------------- init ----------------
__global__ void init_zero_kernel() {
    int tid = threadIdx.x;
    if (tid == 0) { g_psum = 0.0; g_psumsq = 0.0; }
    for (int i = tid; i < BB*LL*CC; i += 256) g_sums[i] = 0.f;
    for (int i = tid; i < BB*LL; i += 256) g_counts[i] = 0.f;
}

// ---------------- Wlo -> mma A-fragment order (all 4 layers) ----------------
__global__ void wfrag_kernel(const float* __restrict__ w) {
    int idx = blockIdx.x * 256 + threadIdx.x;
    if (idx >= 18432) return;
    int lane = idx & 31;
    int r = idx >> 5;
    int cogrp = r & 3; r >>= 2;
    int kc = r & 3; r >>= 2;
    int tap = r % 9; int l = r / 9;
    int row = cogrp*16 + (lane >> 2);
    int c0 = kc*16 + (lane & 3)*2;
    #define WLO(co, ci) ({ float v_ = w[((size_t)((l)*64 + (co))*64 + (ci))*9 + tap]; \
                           v_ - bf_round(v_); })
    uint4 o;
    o.x = pack_cvt(WLO(row,     c0),   WLO(row,     c0+1));
    o.y = pack_cvt(WLO(row+8,   c0),   WLO(row+8,   c0+1));
    o.z = pack_cvt(WLO(row,     c0+8), WLO(row,     c0+9));
    o.w = pack_cvt(WLO(row+8,   c0+8), WLO(row+8,   c0+9));
    #undef WLO
    g_wfragLo[((l*9 + tap)*4 + kc)*128 + cogrp*32 + lane] = o;
}

// ---------------- features (ch-major fp32) -> pixel-major bf16 hi/lo ----------------
__global__ __launch_bounds__(256)
void trans_kernel(const float* __restrict__ in, uint16_t* __restrict__ outHi) {
    __shared__ float s[64][129];
    const int blk = blockIdx.x;
    const int sl = blk >> 7;
    const int h  = blk & 127;
    const int b = sl >> 3, d = sl & 7;
    const int tid = threadIdx.x;
    for (int i = tid; i < 8192; i += 256) {
        int c = i >> 7, w = i & 127;
        s[c][w] = in[((size_t)(b*64 + c)*8 + d)*16384 + h*128 + w];
    }
    __syncthreads();
    for (int i = tid; i < 1024; i += 256) {
        int w = i >> 3, ch = i & 7;
        uint32_t hw[4], lw[4];
        #pragma unroll
        for (int j = 0; j < 4; j++) {
            float v0 = s[ch*8 + 2*j][w];
            float v1 = s[ch*8 + 2*j + 1][w];
            __nv_bfloat16 h0 = __float2bfloat16(v0);
            __nv_bfloat16 h1 = __float2bfloat16(v1);
            hw[j] = pack_bits(h0, h1);
            lw[j] = pack_cvt(v0 - __bfloat162float(h0), v1 - __bfloat162float(h1));
        }
        size_t e = (((size_t)sl*128 + h)*128 + w)*64 + ch*8;
        *(uint4*)(outHi + e) = make_uint4(hw[0], hw[1], hw[2], hw[3]);
        *(uint4*)(outHi + HALF_ELEMS + e) = make_uint4(lw[0], lw[1], lw[2], lw[3]);
    }
}

// ================= mma.sync conv (pipelined) =================
// Tile: 64 px x 64 co. Merged K-loop does Whi*Xhi + Whi*Xlo + Wlo*Xhi into one acc.
// Whi in smem (ldmatrix); Wlo from gmem fragment table; Xhi/Xlo double-buffered
// in smem via cp.async overlapped with the previous tile's MMAs.
#define SM_W_HI  0            // 73728
#define SM_IN    73728        // 2 x 50688
#define SM_S     175104       // 64*65*4 = 16640
#define SM_BIAS  191744       // 256
#define CONV_SMEM 192000
#define IN_ROW   8448         // 66 px * 128 B
#define BUF_STRIDE 50688
#define GRIDC 148

__global__ __launch_bounds__(256, 1)
void conv_mma_kernel(const uint16_t* __restrict__ inBuf,   // Hi, Lo at +HALF_ELEMS
                     void* __restrict__ outP,
                     const float* __restrict__ wsrc,       // [co][ci][9] this layer
                     const uint4* __restrict__ wfrag,      // Wlo frags this layer
                     const float* __restrict__ bias,
                     int mode)                             // 0: bf16 hi/lo px-major, 1: fp32 ch-major
{
    extern __shared__ char smem[];
    const uint32_t sb = smem_u32(smem);
    float* S = (float*)(smem + SM_S);
    float* sBias = (float*)(smem + SM_BIAS);
    const int tid = threadIdx.x;
    const int wid = tid >> 5, lane = tid & 31;

    // ---- Whi -> smem (swizzled rows of 128B) ----
    for (int i = tid; i < 18432; i += 256) {
        int tap = i >> 11; int r2 = i & 2047;
        int co = r2 >> 5; int cp = r2 & 31; int ci = cp*2;
        float wa = wsrc[(co*64 + ci)*9 + tap];
        float wb = wsrc[(co*64 + ci + 1)*9 + tap];
        uint32_t hi = pack_bits(__float2bfloat16(wa), __float2bfloat16(wb));
        uint32_t off = (uint32_t)(co*128 + cp*4);
        uint32_t sw = off ^ ((off >> 3) & 0x70);
        *(uint32_t*)(smem + SM_W_HI + tap*8192 + sw) = hi;
    }
    if (tid < 64) sBias[tid] = bias[tid];
    __syncthreads();

    // warp tiling: 4 warps along co (16 each), 2 along px (32 each)
    const int co_base = (wid & 3) * 16;
    const int cogrp = wid & 3;
    const int px_base = (wid >> 2) * 32;
    const int am  = (lane & 7) + ((lane >> 3) & 1) * 8;
    const int akh = lane >> 4;
    const int bn  = (lane & 7) + (lane >> 4) * 8;
    const int bkh = (lane >> 3) & 1;
    const uint32_t axor = (uint32_t)((am & 7) << 4);

    // ---- staging (cp.async, zfill halo) ----
    auto stage_tile = [&](int buf, int t) {
        const int sl = t >> 8;
        const int h  = (t >> 1) & 127;
        const int w0 = (t & 1) << 6;
        const uint32_t dstBase = sb + SM_IN + buf*BUF_STRIDE;
        #pragma unroll 1
        for (int i = tid; i < 3168; i += 256) {
            int bsel = (i >= 1584) ? 1 : 0;
            int r = i - bsel*1584;
            int ky = r / 528; int rem = r - ky*528;
            int px = rem >> 3; int ch = rem & 7;
            int gh = h + ky - 1, gw = w0 - 1 + px;
            uint32_t ok = ((unsigned)gh < 128u) && ((unsigned)gw < 128u);
            int cgh = ok ? gh : 0, cgw = ok ? gw : 0;
            const uint16_t* src = inBuf + (size_t)bsel*HALF_ELEMS +
                    (((size_t)sl*128 + cgh)*128 + cgw)*64 + ch*8;
            uint32_t dst = dstBase + bsel*25344 + ky*IN_ROW +
                           px*128 + ((ch ^ (px & 7)) << 4);
            CP_ASYNC16(dst, src, ok ? 16u : 0u);
        }
        CP_COMMIT();
    };

    int t = blockIdx.x;
    int curbuf = 0;
    stage_tile(0, t);

    for (; t < 4096; t += GRIDC) {
        const int sl = t >> 8;
        const int h  = (t >> 1) & 127;
        const int w0 = (t & 1) << 6;
        const int nt = t + GRIDC;

        if (nt < 4096) { stage_tile(curbuf ^ 1, nt); CP_WAIT1(); }
        else           { CP_WAIT0(); }
        __syncthreads();

        const uint32_t inHi = sb + SM_IN + curbuf*BUF_STRIDE;
        const uint32_t inLo = inHi + 25344;

        float acc[4][4] = {};
        #pragma unroll 1
        for (int ky = 0; ky < 3; ky++) {
            const uint32_t bHrow = inHi + ky*IN_ROW;
            const uint32_t bLrow = inLo + ky*IN_ROW;
            #pragma unroll
            for (int kx = 0; kx < 3; kx++) {
                const int tap = ky*3 + kx;
                const uint32_t aT = sb + SM_W_HI + tap*8192 +
                                    (uint32_t)((co_base + am)*128);
                const int spx1 = px_base + bn + kx;
                const int spx2 = spx1 + 16;
                const uint32_t bH1 = bHrow + spx1*128;
                const uint32_t bH2 = bHrow + spx2*128;
                const uint32_t bL1 = bLrow + spx1*128;
                const uint32_t bL2 = bLrow + spx2*128;
                const uint32_t bx1 = (uint32_t)((spx1 & 7) << 4);
                const uint32_t bx2 = (uint32_t)((spx2 & 7) << 4);
                const uint4* wlp = wfrag + (tap*4)*128 + cogrp*32 + lane;
                #pragma unroll
                for (int kc = 0; kc < 4; kc++) {
                    const uint32_t ku  = (uint32_t)(kc*32 + akh*16);
                    const uint32_t kub = (uint32_t)(kc*32 + bkh*16);
                    uint32_t a0,a1,a2,a3;
                    LDSM4(a0,a1,a2,a3, aT + (ku ^ axor));
                    uint4 al = wlp[kc*128];
                    uint32_t h0,h1,h2,h3, h4,h5,h6,h7;
                    LDSM4(h0,h1,h2,h3, bH1 + (kub ^ bx1));
                    LDSM4(h4,h5,h6,h7, bH2 + (kub ^ bx2));
                    uint32_t l0,l1,l2,l3, l4,l5,l6,l7;
                    LDSM4(l0,l1,l2,l3, bL1 + (kub ^ bx1));
                    LDSM4(l4,l5,l6,l7, bL2 + (kub ^ bx2));
                    MMA16816(acc[0], a0,a1,a2,a3, h0,h1);
                    MMA16816(acc[1], a0,a1,a2,a3, h2,h3);
                    MMA16816(acc[2], a0,a1,a2,a3, h4,h5);
                    MMA16816(acc[3], a0,a1,a2,a3, h6,h7);
                    MMA16816(acc[0], a0,a1,a2,a3, l0,l1);
                    MMA16816(acc[1], a0,a1,a2,a3, l2,l3);
                    MMA16816(acc[2], a0,a1,a2,a3, l4,l5);
                    MMA16816(acc[3], a0,a1,a2,a3, l6,l7);
                    MMA16816(acc[0], al.x,al.y,al.z,al.w, h0,h1);
                    MMA16816(acc[1], al.x,al.y,al.z,al.w, h2,h3);
                    MMA16816(acc[2], al.x,al.y,al.z,al.w, h4,h5);
                    MMA16816(acc[3], al.x,al.y,al.z,al.w, h6,h7);
                }
            }
        }

        // ---- fragments -> S[px][co] ----
        #pragma unroll
        for (int j = 0; j < 4; j++) {
            int pc = px_base + 8*j + 2*(lane & 3);
            int mr = co_base + (lane >> 2);
            S[pc*65 + mr]           = acc[j][0];
            S[(pc+1)*65 + mr]       = acc[j][1];
            S[pc*65 + mr + 8]       = acc[j][2];
            S[(pc+1)*65 + mr + 8]   = acc[j][3];
        }
        __syncthreads();

        // ---- epilogue ----
        if (mode == 0) {
            const int px = tid >> 2, cb = (tid & 3) * 16;
            uint32_t hw[8], lw[8];
            #pragma unroll
            for (int j = 0; j < 8; j++) {
                float v0 = fmaxf(S[px*65 + cb + 2*j]     + sBias[cb + 2*j],     0.f);
                float v1 = fmaxf(S[px*65 + cb + 2*j + 1] + sBias[cb + 2*j + 1], 0.f);
                __nv_bfloat16 h0 = __float2bfloat16(v0);
                __nv_bfloat16 h1 = __float2bfloat16(v1);
                hw[j] = pack_bits(h0, h1);
                lw[j] = pack_cvt(v0 - __bfloat162float(h0), v1 - __bfloat162float(h1));
            }
            uint16_t* ob = (uint16_t*)outP;
            size_t e = (((size_t)sl*128 + h)*128 + (w0 + px))*64 + cb;
            *(uint4*)(ob + e)     = make_uint4(hw[0], hw[1], hw[2], hw[3]);
            *(uint4*)(ob + e + 8) = make_uint4(hw[4], hw[5], hw[6], hw[7]);
            *(uint4*)(ob + HALF_ELEMS + e)     = make_uint4(lw[0], lw[1], lw[2], lw[3]);
            *(uint4*)(ob + HALF_ELEMS + e + 8) = make_uint4(lw[4], lw[5], lw[6], lw[7]);
        } else {
            const int co = tid >> 2, pb = (tid & 3) * 16;
            const int b_ = sl >> 3, d_ = sl & 7;
            const float bv = sBias[co];
            float* ob = (float*)outP +
                ((size_t)(b_*64 + co)*8 + d_)*16384 + h*128 + w0 + pb;
            #pragma unroll
            for (int q = 0; q < 4; q++) {
                float4 o;
                o.x = fmaxf(S[(pb + 4*q + 0)*65 + co] + bv, 0.f);
                o.y = fmaxf(S[(pb + 4*q + 1)*65 + co] + bv, 0.f);
                o.z = fmaxf(S[(pb + 4*q + 2)*65 + co] + bv, 0.f);
                o.w = fmaxf(S[(pb + 4*q + 3)*65 + co] + bv, 0.f);
                *(float4*)(ob + 4*q) = o;
            }
        }
        curbuf ^= 1;
    }
}

// ---------------- segment sums ----------------
#define VCH 2048
__global__ __launch_bounds__(256)
void segsum_kernel(const float* __restrict__ x, const int* __restrict__ labels)
{
    __shared__ float sAcc[LL*CC];
    __shared__ float sCnt[LL];
    __shared__ int sLab[VCH];
    const int b = blockIdx.y;
    const int v0 = blockIdx.x * VCH;
    const int tid = threadIdx.x;

    for (int i = tid; i < LL*CC; i += 256) sAcc[i] = 0.f;
    for (int i = tid; i < LL; i += 256) sCnt[i] = 0.f;
    for (int i = tid; i < VCH; i += 256) sLab[i] = labels[(size_t)b*VV + v0 + i];
    __syncthreads();

    for (int i = tid; i < VCH; i += 256) atomicAdd(&sCnt[sLab[i]], 1.f);
    const float* xb = x + (size_t)b*64*VV + v0;
    for (int c = 0; c < 64; c++) {
        const float* xc = xb + (size_t)c*VV;
        for (int i = tid; i < VCH; i += 256)
            atomicAdd(&sAcc[sLab[i]*64 + c], xc[i]);
    }
    __syncthreads();
    for (int i = tid; i < LL*CC; i += 256) atomicAdd(&g_sums[b*LL*CC + i], sAcc[i]);
    for (int i = tid; i < LL; i += 256) atomicAdd(&g_counts[b*LL + i], sCnt[i]);
}

// ---------------- inst features + mask_kernel linear ----------------
__global__ __launch_bounds__(256)
void instfeat_kernel(const float* __restrict__ embed, const float* __restrict__ mk_w,
                     const float* __restrict__ mk_b, float* __restrict__ if_out,
                     int write_if)
{
    __shared__ float sInst[NN*CC];
    __shared__ float sWT[CC*KD];
    const int b = blockIdx.x;
    const int tid = threadIdx.x;

    for (int idx = tid; idx < CC*KD; idx += 256) {
        int kd = idx & 63, c = idx >> 6;
        sWT[c*64 + kd] = mk_w[kd*64 + c];
    }
    for (int idx = tid; idx < 100*CC; idx += 256) {
        int n = idx >> 6, c = idx & 63;
        int l = n + 1;
        float cnt = fmaxf(g_counts[b*LL + l], 1.f);
        sInst[idx] = g_sums[(b*LL + l)*64 + c] / cnt;
    }
    for (int idx = tid; idx < NLM*CC; idx += 256)
        sInst[100*CC + idx] = embed[idx];
    __syncthreads();

    if (write_if)
        for (int idx = tid; idx < NN*CC; idx += 256)
            if_out[(size_t)b*NN*CC + idx] = sInst[idx];

    for (int idx = tid; idx < NN*KD; idx += 256) {
        int n = idx >> 6, kd = idx & 63;
        const float* ip = sInst + n*64;
        float a = mk_b[kd];
        #pragma unroll
        for (int c = 0; c < 64; c++)
            a = fmaf(ip[c], sWT[c*64 + kd], a);
        g_kraw[(size_t)b*NN*KD + idx] = a;
    }
}

// ---------------- BatchNorm1d over (B,N) per KD channel ----------------
__global__ void bnk_kernel(const float* __restrict__ gamma, const float* __restrict__ beta,
                           float* __restrict__ pk_out, int write_pk)
{
    const int kd = threadIdx.x;
    double s = 0.0, sq = 0.0;
    for (int i = 0; i < BB*NN; i++) {
        float v = g_kraw[i*64 + kd];
        s += (double)v; sq += (double)v * v;
    }
    double mean = s / (double)(BB*NN);
    double var = sq / (double)(BB*NN) - mean*mean;
    float inv = (float)(1.0 / sqrt(var + (double)EPSV));
    float g = gamma[kd], be = beta[kd], m = (float)mean;
    for (int i = 0; i < BB*NN; i++) {
        float v = (g_kraw[i*64 + kd] - m) * inv * g + be;
        g_knorm[i*64 + kd] = v;
        if (write_pk) pk_out[i*64 + kd] = v;
    }
}

// ---------------- bmm + stats ----------------
__global__ __launch_bounds__(256)
void bmm_kernel(const float* __restrict__ mf, float* __restrict__ pm)
{
    __shared__ __align__(16) float sK[NN*KD];
    __shared__ float rs[256], rq[256];
    const int b = blockIdx.y;
    const int tid = threadIdx.x;
    const int v = blockIdx.x * 256 + tid;

    for (int i = tid; i < NN*KD; i += 256) sK[i] = g_knorm[b*NN*KD + i];
    __syncthreads();

    float mfv[64];
    const float* mb = mf + (size_t)b*64*VV + v;
    #pragma unroll
    for (int k = 0; k < 64; k++) mfv[k] = mb[(size_t)k*VV];

    float psum = 0.f, psq = 0.f;
    float* po = pm + (size_t)b*NN*VV + v;
    #pragma unroll 4
    for (int n = 0; n < NN; n++) {
        const float4* kp = (const float4*)(sK + n*64);
        float a = 0.f;
        #pragma unroll
        for (int kk = 0; kk < 16; kk++) {
            float4 kv = kp[kk];
            a = fmaf(kv.x, mfv[4*kk+0], a);
            a = fmaf(kv.y, mfv[4*kk+1], a);
            a = fmaf(kv.z, mfv[4*kk+2], a);
            a = fmaf(kv.w, mfv[4*kk+3], a);
        }
        po[(size_t)n*VV] = a;
        psum += a; psq += a*a;
    }
    rs[tid] = psum; rq[tid] = psq;
    __syncthreads();
    for (int s = 128; s > 0; s >>= 1) {
        if (tid < s) { rs[tid] += rs[tid+s]; rq[tid] += rq[tid+s]; }
        __syncthreads();
    }
    if (tid == 0) {
        atomicAdd(&g_psum, (double)rs[0]);
        atomicAdd(&g_psumsq, (double)rq[0]);
    }
}

// ---------------- global BN over pred_masks ----------------
__global__ void norm_masks_kernel(float* __restrict__ pm,
                                  const float* __restrict__ gam,
                                  const float* __restrict__ bet)
{
    const double N = (double)PM_ELEMS;
    double mean = g_psum / N;
    double var = g_psumsq / N - mean*mean;
    float inv = (float)(1.0 / sqrt(var + (double)EPSV));
    float g = gam[0] * inv;
    float m = (float)mean;
    float be = bet[0];
    float4* p = (float4*)pm;
    const int n4 = PM_ELEMS / 4;
    for (int i = blockIdx.x*blockDim.x + threadIdx.x; i < n4; i += gridDim.x*blockDim.x) {
        float4 v = p[i];
        v.x = (v.x - m)*g + be;
        v.y = (v.y - m)*g + be;
        v.z = (v.z - m)*g + be;
        v.w = (v.w - m)*g + be;
        p[i] = v;
    }
}

// ---------------- launch ----------------
extern "C" void kernel_launch(void* const* d_in, const int* in_sizes, int n_in,
                              void* d_out, int out_size)
{
    const float* features      = (const float*)d_in[0];
    const float* mask_features = (const float*)d_in[1];
    const float* conv_w        = (const float*)d_in[2];
    const float* conv_b        = (const float*)d_in[3];
    const float* embed         = (const float*)d_in[4];
    const float* mk_w          = (const float*)d_in[5];
    const float* mk_b          = (const float*)d_in[6];
    const float* nk_gamma      = (const float*)d_in[7];
    const float* nk_beta       = (const float*)d_in[8];
    const float* nl_gamma      = (const float*)d_in[9];
    const float* nl_beta       = (const float*)d_in[10];
    const int*   init_masks    = (const int*)d_in[11];
    float* out = (float*)d_out;

    float *bufA = nullptr, *bufB = nullptr;
    uint4* wfrag = nullptr;
    cudaGetSymbolAddress((void**)&bufA, g_bufA);
    cudaGetSymbolAddress((void**)&bufB, g_bufB);
    cudaGetSymbolAddress((void**)&wfrag, g_wfragLo);
    uint16_t* hA = (uint16_t*)bufA;
    uint16_t* hB = (uint16_t*)bufB;

    int full = (out_size >= OUT_FULL) ? 1 : 0;
    int masks_only = (!full && out_size >= PM_ELEMS) ? 1 : 0;

    float* xout  = full ? out : bufB;
    float* ifout = full ? (out + X_ELEMS) : out;
    float* pmout = full ? (out + X_ELEMS + IF_ELEMS) : (masks_only ? out : bufB);
    float* pkout = full ? (out + X_ELEMS + IF_ELEMS + PM_ELEMS) : out;

    static int attr_done = 0;
    if (!attr_done) {
        cudaFuncSetAttribute(conv_mma_kernel,
                             cudaFuncAttributeMaxDynamicSharedMemorySize, CONV_SMEM);
        attr_done = 1;
    }

    init_zero_kernel<<<1, 256>>>();
    wfrag_kernel<<<72, 256>>>(conv_w);
    trans_kernel<<<2048, 256>>>(features, hB);

    conv_mma_kernel<<<GRIDC, 256, CONV_SMEM>>>(hB, hA,   conv_w + 0*36864, wfrag + 0*4608, conv_b + 0,   0);
    conv_mma_kernel<<<GRIDC, 256, CONV_SMEM>>>(hA, hB,   conv_w + 1*36864, wfrag + 1*4608, conv_b + 64,  0);
    conv_mma_kernel<<<GRIDC, 256, CONV_SMEM>>>(hB, hA,   conv_w + 2*36864, wfrag + 2*4608, conv_b + 128, 0);
    conv_mma_kernel<<<GRIDC, 256, CONV_SMEM>>>(hA, xout, conv_w + 3*36864, wfrag + 3*4608, conv_b + 192, 1);

    segsum_kernel<<<dim3(VV/VCH, BB), 256>>>(xout, init_masks);
    instfeat_kernel<<<BB, 256>>>(embed, mk_w, mk_b, ifout, full);
    bnk_kernel<<<1, 64>>>(nk_gamma, nk_beta, pkout, full);

    if (full || masks_only) {
        bmm_kernel<<<dim3(VV/256, BB), 256>>>(mask_features, pmout);
        norm_masks_kernel<<<4096, 256>>>(pmout, nl_gamma, nl_beta);
    }
}

// round 7
// speedup vs baseline: 1.8474x; 1.0449x over previous
#include <cuda_runtime.h>
#include <cuda_bf16.h>
#include <math.h>
#include <stdint.h>

// Problem constants
#define BB 2
#define CC 64
#define DD 8
#define HH 128
#define WW 128
#define VV (DD*HH*WW)          // 131072
#define LL 101
#define KD 64
#define NLM 20
#define NN (100 + NLM)         // 120
#define EPSV 1e-3f

#define X_ELEMS   (BB*CC*VV)          // 16777216
#define IF_ELEMS  (BB*NN*CC)
#define PM_ELEMS  (BB*NN*VV)
#define PK_ELEMS  (BB*NN*KD)
#define OUT_FULL  (X_ELEMS + IF_ELEMS + PM_ELEMS + PK_ELEMS)

#define HALF_ELEMS 16777216           // bf16 elems per (hi|lo) half of a scratch buffer

// ---------------- device scratch ----------------
__device__ float g_bufA[X_ELEMS];     // Hi bf16 [0..16M) + Lo bf16 [16M..32M)
__device__ float g_bufB[X_ELEMS];
__device__ uint4 g_wfragLo[4*9*4*4*32];   // Wlo in mma-A fragment order
__device__ float g_sums[BB*LL*CC];
__device__ float g_counts[BB*LL];
__device__ float g_kraw[BB*NN*KD];
__device__ float g_knorm[BB*NN*KD];
__device__ double g_psum;
__device__ double g_psumsq;

// ================= helpers =================
typedef unsigned long long u64t;
__device__ __forceinline__ uint32_t smem_u32(const void* p) {
    uint32_t a;
    asm("{ .reg .u64 t; cvta.to.shared.u64 t, %1; cvt.u32.u64 %0, t; }"
        : "=r"(a) : "l"(p));
    return a;
}
__device__ __forceinline__ uint32_t pack_bits(__nv_bfloat16 lo, __nv_bfloat16 hi) {
    return (uint32_t)__bfloat16_as_ushort(lo) | ((uint32_t)__bfloat16_as_ushort(hi) << 16);
}
__device__ __forceinline__ uint32_t pack_cvt(float lo, float hi) {
    uint32_t r;
    asm("cvt.rn.bf16x2.f32 %0, %1, %2;" : "=r"(r) : "f"(hi), "f"(lo));
    return r;
}
__device__ __forceinline__ float bf_round(float x) {
    return __bfloat162float(__float2bfloat16(x));
}
__device__ __forceinline__ u64t fma2(u64t a, u64t b, u64t c) {
    u64t d;
    asm("fma.rn.f32x2 %0, %1, %2, %3;" : "=l"(d) : "l"(a), "l"(b), "l"(c));
    return d;
}
__device__ __forceinline__ u64t dup2(float v) {
    u64t d;
    asm("mov.b64 %0, {%1, %1};" : "=l"(d) : "f"(v));
    return d;
}
__device__ __forceinline__ u64t pack2(float a, float b) {
    u64t d;
    asm("mov.b64 %0, {%1, %2};" : "=l"(d) : "f"(a), "f"(b));
    return d;
}
__device__ __forceinline__ float2 unpack2(u64t v) {
    float2 r;
    asm("mov.b64 {%0, %1}, %2;" : "=f"(r.x), "=f"(r.y) : "l"(v));
    return r;
}

#define LDSM4(r0,r1,r2,r3, addr) \
    asm volatile("ldmatrix.sync.aligned.m8n8.x4.shared.b16 {%0,%1,%2,%3}, [%4];" \
        : "=r"(r0),"=r"(r1),"=r"(r2),"=r"(r3) : "r"(addr))

#define MMA16816(d, a0,a1,a2,a3, b0,b1) \
    asm volatile("mma.sync.aligned.m16n8k16.row.col.f32.bf16.bf16.f32 " \
        "{%0,%1,%2,%3}, {%4,%5,%6,%7}, {%8,%9}, {%0,%1,%2,%3};" \
        : "+f"((d)[0]), "+f"((d)[1]), "+f"((d)[2]), "+f"((d)[3]) \
        : "r"(a0),"r"(a1),"r"(a2),"r"(a3), "r"(b0),"r"(b1))

#define CP_ASYNC16(dst, src, n) \
    asm volatile("cp.async.cg.shared.global [%0], [%1], 16, %2;" \
        :: "r"(dst), "l"(src), "r"(n) : "memory")
#define CP_COMMIT() asm volatile("cp.async.commit_group;" ::: "memory")
#define CP_WAIT0()  asm volatile("cp.async.wait_group 0;" ::: "memory")
#define CP_WAIT1()  asm volatile("cp.async.wait_group 1;" ::: "memory")

// ---------------- init ----------------
__global__ void init_zero_kernel() {
    int tid = threadIdx.x;
    if (tid == 0) { g_psum = 0.0; g_psumsq = 0.0; }
    for (int i = tid; i < BB*LL*CC; i += 256) g_sums[i] = 0.f;
    for (int i = tid; i < BB*LL; i += 256) g_counts[i] = 0.f;
}

// ---------------- Wlo -> mma A-fragment order (all 4 layers) ----------------
__global__ void wfrag_kernel(const float* __restrict__ w) {
    int idx = blockIdx.x * 256 + threadIdx.x;
    if (idx >= 18432) return;
    int lane = idx & 31;
    int r = idx >> 5;
    int cogrp = r & 3; r >>= 2;
    int kc = r & 3; r >>= 2;
    int tap = r % 9; int l = r / 9;
    int row = cogrp*16 + (lane >> 2);
    int c0 = kc*16 + (lane & 3)*2;
    #define WLO(co, ci) ({ float v_ = w[((size_t)((l)*64 + (co))*64 + (ci))*9 + tap]; \
                           v_ - bf_round(v_); })
    uint4 o;
    o.x = pack_cvt(WLO(row,     c0),   WLO(row,     c0+1));
    o.y = pack_cvt(WLO(row+8,   c0),   WLO(row+8,   c0+1));
    o.z = pack_cvt(WLO(row,     c0+8), WLO(row,     c0+9));
    o.w = pack_cvt(WLO(row+8,   c0+8), WLO(row+8,   c0+9));
    #undef WLO
    g_wfragLo[((l*9 + tap)*4 + kc)*128 + cogrp*32 + lane] = o;
}

// ---------------- features (ch-major fp32) -> pixel-major bf16 hi/lo ----------------
__global__ __launch_bounds__(256)
void trans_kernel(const float* __restrict__ in, uint16_t* __restrict__ outHi) {
    __shared__ float s[64][129];
    const int blk = blockIdx.x;
    const int sl = blk >> 7;
    const int h  = blk & 127;
    const int b = sl >> 3, d = sl & 7;
    const int tid = threadIdx.x;
    for (int i = tid; i < 8192; i += 256) {
        int c = i >> 7, w = i & 127;
        s[c][w] = in[((size_t)(b*64 + c)*8 + d)*16384 + h*128 + w];
    }
    __syncthreads();
    for (int i = tid; i < 1024; i += 256) {
        int w = i >> 3, ch = i & 7;
        uint32_t hw[4], lw[4];
        #pragma unroll
        for (int j = 0; j < 4; j++) {
            float v0 = s[ch*8 + 2*j][w];
            float v1 = s[ch*8 + 2*j + 1][w];
            __nv_bfloat16 h0 = __float2bfloat16(v0);
            __nv_bfloat16 h1 = __float2bfloat16(v1);
            hw[j] = pack_bits(h0, h1);
            lw[j] = pack_cvt(v0 - __bfloat162float(h0), v1 - __bfloat162float(h1));
        }
        size_t e = (((size_t)sl*128 + h)*128 + w)*64 + ch*8;
        *(uint4*)(outHi + e) = make_uint4(hw[0], hw[1], hw[2], hw[3]);
        *(uint4*)(outHi + HALF_ELEMS + e) = make_uint4(lw[0], lw[1], lw[2], lw[3]);
    }
}

// ================= mma.sync conv (pipelined) =================
#define SM_W_HI  0            // 73728
#define SM_IN    73728        // 2 x 50688
#define SM_S     175104       // 64*65*4 = 16640
#define SM_BIAS  191744       // 256
#define CONV_SMEM 192000
#define IN_ROW   8448         // 66 px * 128 B
#define BUF_STRIDE 50688
#define GRIDC 148

__global__ __launch_bounds__(256, 1)
void conv_mma_kernel(const uint16_t* __restrict__ inBuf,   // Hi, Lo at +HALF_ELEMS
                     void* __restrict__ outP,
                     const float* __restrict__ wsrc,       // [co][ci][9] this layer
                     const uint4* __restrict__ wfrag,      // Wlo frags this layer
                     const float* __restrict__ bias,
                     int mode)
{
    extern __shared__ char smem[];
    const uint32_t sb = smem_u32(smem);
    float* S = (float*)(smem + SM_S);
    float* sBias = (float*)(smem + SM_BIAS);
    const int tid = threadIdx.x;
    const int wid = tid >> 5, lane = tid & 31;

    // ---- Whi -> smem (swizzled rows of 128B) ----
    for (int i = tid; i < 18432; i += 256) {
        int tap = i >> 11; int r2 = i & 2047;
        int co = r2 >> 5; int cp = r2 & 31; int ci = cp*2;
        float wa = wsrc[(co*64 + ci)*9 + tap];
        float wb = wsrc[(co*64 + ci + 1)*9 + tap];
        uint32_t hi = pack_bits(__float2bfloat16(wa), __float2bfloat16(wb));
        uint32_t off = (uint32_t)(co*128 + cp*4);
        uint32_t sw = off ^ ((off >> 3) & 0x70);
        *(uint32_t*)(smem + SM_W_HI + tap*8192 + sw) = hi;
    }
    if (tid < 64) sBias[tid] = bias[tid];
    __syncthreads();

    // warp tiling
    const int co_base = (wid & 3) * 16;
    const int cogrp = wid & 3;
    const int px_base = (wid >> 2) * 32;
    const int am  = (lane & 7) + ((lane >> 3) & 1) * 8;
    const int akh = lane >> 4;
    const int bn  = (lane & 7) + (lane >> 4) * 8;
    const int bkh = (lane >> 3) & 1;
    const uint32_t axor = (uint32_t)((am & 7) << 4);

    // ---- precompute staging metadata (tile-invariant) ----
    // meta: dst(16) | ky(2)@16 | px(7)@18 | ch(3)@25 | bsel(1)@28 | valid(1)@31
    uint32_t meta[13];
    #pragma unroll
    for (int j = 0; j < 13; j++) {
        int i = tid + j*256;
        if (i < 3168) {
            int bsel = (i >= 1584) ? 1 : 0;
            int r = i - bsel*1584;
            int ky = r / 528; int rem = r - ky*528;
            int px = rem >> 3; int ch = rem & 7;
            uint32_t dsto = (uint32_t)(bsel*25344 + ky*IN_ROW + px*128 +
                                       ((ch ^ (px & 7)) << 4));
            meta[j] = dsto | ((uint32_t)ky << 16) | ((uint32_t)px << 18) |
                      ((uint32_t)ch << 25) | ((uint32_t)bsel << 28) | (1u << 31);
        } else meta[j] = 0;
    }

    auto stage_tile = [&](int buf, int t) {
        const int sl = t >> 8;
        const int h  = (t >> 1) & 127;
        const int w0 = (t & 1) << 6;
        const uint32_t dstBase = sb + SM_IN + buf*BUF_STRIDE;
        const uint16_t* base = inBuf + (size_t)sl * 1048576;
        #pragma unroll
        for (int j = 0; j < 13; j++) {
            uint32_t m = meta[j];
            if (m & (1u << 31)) {
                int ky = (m >> 16) & 3;
                int px = (m >> 18) & 127;
                int ch = (m >> 25) & 7;
                int bsel = (m >> 28) & 1;
                int gh = h + ky - 1, gw = w0 + px - 1;
                uint32_t ok = (((unsigned)gh < 128u) & ((unsigned)gw < 128u)) ? 1u : 0u;
                int cgh = ok ? gh : 0, cgw = ok ? gw : 0;
                const uint16_t* src = base + (size_t)bsel*HALF_ELEMS +
                        (((uint32_t)(cgh*128 + cgw)) << 6) + (ch << 3);
                CP_ASYNC16(dstBase + (m & 0xFFFFu), src, ok ? 16u : 0u);
            }
        }
        CP_COMMIT();
    };

    int t = blockIdx.x;
    int curbuf = 0;
    stage_tile(0, t);

    for (; t < 4096; t += GRIDC) {
        const int sl = t >> 8;
        const int h  = (t >> 1) & 127;
        const int w0 = (t & 1) << 6;
        const int nt = t + GRIDC;

        if (nt < 4096) { stage_tile(curbuf ^ 1, nt); CP_WAIT1(); }
        else           { CP_WAIT0(); }
        __syncthreads();

        const uint32_t inHi = sb + SM_IN + curbuf*BUF_STRIDE;
        const uint32_t inLo = inHi + 25344;

        float acc[4][4] = {};
        #pragma unroll
        for (int ky = 0; ky < 3; ky++) {
            const uint32_t bHrow = inHi + ky*IN_ROW;
            const uint32_t bLrow = inLo + ky*IN_ROW;
            #pragma unroll
            for (int kx = 0; kx < 3; kx++) {
                const int tap = ky*3 + kx;
                const uint32_t aT = sb + SM_W_HI + tap*8192 +
                                    (uint32_t)((co_base + am)*128);
                const int spx1 = px_base + bn + kx;
                const int spx2 = spx1 + 16;
                const uint32_t bH1 = bHrow + spx1*128;
                const uint32_t bH2 = bHrow + spx2*128;
                const uint32_t bL1 = bLrow + spx1*128;
                const uint32_t bL2 = bLrow + spx2*128;
                const uint32_t bx1 = (uint32_t)((spx1 & 7) << 4);
                const uint32_t bx2 = (uint32_t)((spx2 & 7) << 4);
                const uint4* wlp = wfrag + (tap*4)*128 + cogrp*32 + lane;
                #pragma unroll
                for (int kc = 0; kc < 4; kc++) {
                    const uint32_t ku  = (uint32_t)(kc*32 + akh*16);
                    const uint32_t kub = (uint32_t)(kc*32 + bkh*16);
                    uint32_t a0,a1,a2,a3;
                    LDSM4(a0,a1,a2,a3, aT + (ku ^ axor));
                    uint4 al = wlp[kc*128];
                    uint32_t h0,h1,h2,h3, h4,h5,h6,h7;
                    LDSM4(h0,h1,h2,h3, bH1 + (kub ^ bx1));
                    LDSM4(h4,h5,h6,h7, bH2 + (kub ^ bx2));
                    uint32_t l0,l1,l2,l3, l4,l5,l6,l7;
                    LDSM4(l0,l1,l2,l3, bL1 + (kub ^ bx1));
                    LDSM4(l4,l5,l6,l7, bL2 + (kub ^ bx2));
                    MMA16816(acc[0], a0,a1,a2,a3, h0,h1);
                    MMA16816(acc[1], a0,a1,a2,a3, h2,h3);
                    MMA16816(acc[2], a0,a1,a2,a3, h4,h5);
                    MMA16816(acc[3], a0,a1,a2,a3, h6,h7);
                    MMA16816(acc[0], a0,a1,a2,a3, l0,l1);
                    MMA16816(acc[1], a0,a1,a2,a3, l2,l3);
                    MMA16816(acc[2], a0,a1,a2,a3, l4,l5);
                    MMA16816(acc[3], a0,a1,a2,a3, l6,l7);
                    MMA16816(acc[0], al.x,al.y,al.z,al.w, h0,h1);
                    MMA16816(acc[1], al.x,al.y,al.z,al.w, h2,h3);
                    MMA16816(acc[2], al.x,al.y,al.z,al.w, h4,h5);
                    MMA16816(acc[3], al.x,al.y,al.z,al.w, h6,h7);
                }
            }
        }

        // ---- fragments -> S[px][co] ----
        #pragma unroll
        for (int j = 0; j < 4; j++) {
            int pc = px_base + 8*j + 2*(lane & 3);
            int mr = co_base + (lane >> 2);
            S[pc*65 + mr]           = acc[j][0];
            S[(pc+1)*65 + mr]       = acc[j][1];
            S[pc*65 + mr + 8]       = acc[j][2];
            S[(pc+1)*65 + mr + 8]   = acc[j][3];
        }
        __syncthreads();

        // ---- epilogue ----
        if (mode == 0) {
            const int px = tid >> 2, cb = (tid & 3) * 16;
            uint32_t hw[8], lw[8];
            #pragma unroll
            for (int j = 0; j < 8; j++) {
                float v0 = fmaxf(S[px*65 + cb + 2*j]     + sBias[cb + 2*j],     0.f);
                float v1 = fmaxf(S[px*65 + cb + 2*j + 1] + sBias[cb + 2*j + 1], 0.f);
                __nv_bfloat16 h0 = __float2bfloat16(v0);
                __nv_bfloat16 h1 = __float2bfloat16(v1);
                hw[j] = pack_bits(h0, h1);
                lw[j] = pack_cvt(v0 - __bfloat162float(h0), v1 - __bfloat162float(h1));
            }
            uint16_t* ob = (uint16_t*)outP;
            size_t e = (((size_t)sl*128 + h)*128 + (w0 + px))*64 + cb;
            *(uint4*)(ob + e)     = make_uint4(hw[0], hw[1], hw[2], hw[3]);
            *(uint4*)(ob + e + 8) = make_uint4(hw[4], hw[5], hw[6], hw[7]);
            *(uint4*)(ob + HALF_ELEMS + e)     = make_uint4(lw[0], lw[1], lw[2], lw[3]);
            *(uint4*)(ob + HALF_ELEMS + e + 8) = make_uint4(lw[4], lw[5], lw[6], lw[7]);
        } else {
            const int co = tid >> 2, pb = (tid & 3) * 16;
            const int b_ = sl >> 3, d_ = sl & 7;
            const float bv = sBias[co];
            float* ob = (float*)outP +
                ((size_t)(b_*64 + co)*8 + d_)*16384 + h*128 + w0 + pb;
            #pragma unroll
            for (int q = 0; q < 4; q++) {
                float4 o;
                o.x = fmaxf(S[(pb + 4*q + 0)*65 + co] + bv, 0.f);
                o.y = fmaxf(S[(pb + 4*q + 1)*65 + co] + bv, 0.f);
                o.z = fmaxf(S[(pb + 4*q + 2)*65 + co] + bv, 0.f);
                o.w = fmaxf(S[(pb + 4*q + 3)*65 + co] + bv, 0.f);
                *(float4*)(ob + 4*q) = o;
            }
        }
        curbuf ^= 1;
    }
}

// ---------------- segment sums ----------------
#define VCH 2048
__global__ __launch_bounds__(256)
void segsum_kernel(const float* __restrict__ x, const int* __restrict__ labels)
{
    __shared__ float sAcc[LL*CC];
    __shared__ float sCnt[LL];
    __shared__ int sLab[VCH];
    const int b = blockIdx.y;
    const int v0 = blockIdx.x * VCH;
    const int tid = threadIdx.x;

    for (int i = tid; i < LL*CC; i += 256) sAcc[i] = 0.f;
    for (int i = tid; i < LL; i += 256) sCnt[i] = 0.f;
    for (int i = tid; i < VCH; i += 256) sLab[i] = labels[(size_t)b*VV + v0 + i];
    __syncthreads();

    for (int i = tid; i < VCH; i += 256) atomicAdd(&sCnt[sLab[i]], 1.f);
    const float* xb = x + (size_t)b*64*VV + v0;
    for (int c = 0; c < 64; c++) {
        const float* xc = xb + (size_t)c*VV;
        for (int i = tid; i < VCH; i += 256)
            atomicAdd(&sAcc[sLab[i]*64 + c], xc[i]);
    }
    __syncthreads();
    for (int i = tid; i < LL*CC; i += 256) atomicAdd(&g_sums[b*LL*CC + i], sAcc[i]);
    for (int i = tid; i < LL; i += 256) atomicAdd(&g_counts[b*LL + i], sCnt[i]);
}

// ---------------- inst features + mask_kernel linear ----------------
__global__ __launch_bounds__(256)
void instfeat_kernel(const float* __restrict__ embed, const float* __restrict__ mk_w,
                     const float* __restrict__ mk_b, float* __restrict__ if_out,
                     int write_if)
{
    __shared__ float sInst[NN*CC];
    __shared__ float sWT[CC*KD];
    const int b = blockIdx.x;
    const int tid = threadIdx.x;

    for (int idx = tid; idx < CC*KD; idx += 256) {
        int kd = idx & 63, c = idx >> 6;
        sWT[c*64 + kd] = mk_w[kd*64 + c];
    }
    for (int idx = tid; idx < 100*CC; idx += 256) {
        int n = idx >> 6, c = idx & 63;
        int l = n + 1;
        float cnt = fmaxf(g_counts[b*LL + l], 1.f);
        sInst[idx] = g_sums[(b*LL + l)*64 + c] / cnt;
    }
    for (int idx = tid; idx < NLM*CC; idx += 256)
        sInst[100*CC + idx] = embed[idx];
    __syncthreads();

    if (write_if)
        for (int idx = tid; idx < NN*CC; idx += 256)
            if_out[(size_t)b*NN*CC + idx] = sInst[idx];

    for (int idx = tid; idx < NN*KD; idx += 256) {
        int n = idx >> 6, kd = idx & 63;
        const float* ip = sInst + n*64;
        float a = mk_b[kd];
        #pragma unroll
        for (int c = 0; c < 64; c++)
            a = fmaf(ip[c], sWT[c*64 + kd], a);
        g_kraw[(size_t)b*NN*KD + idx] = a;
    }
}

// ---------------- BatchNorm1d over (B,N) per KD channel (parallel) ----------------
__global__ __launch_bounds__(256)
void bnk_kernel(const float* __restrict__ gamma, const float* __restrict__ beta,
                float* __restrict__ pk_out, int write_pk)
{
    __shared__ float ssum[256], ssq[256];
    __shared__ float sm[64], si[64], sg[64], sbt[64];
    const int tid = threadIdx.x;
    const int kd = tid & 63, q = tid >> 6;
    float s = 0.f, sq = 0.f;
    for (int i = q; i < BB*NN; i += 4) {
        float v = g_kraw[i*64 + kd];
        s += v; sq += v*v;
    }
    ssum[tid] = s; ssq[tid] = sq;
    __syncthreads();
    if (tid < 64) {
        float S = ssum[tid] + ssum[tid+64] + ssum[tid+128] + ssum[tid+192];
        float Q = ssq[tid] + ssq[tid+64] + ssq[tid+128] + ssq[tid+192];
        float mean = S / (float)(BB*NN);
        float var = Q / (float)(BB*NN) - mean*mean;
        sm[tid] = mean;
        si[tid] = rsqrtf(var + EPSV);
        sg[tid] = gamma[tid];
        sbt[tid] = beta[tid];
    }
    __syncthreads();
    for (int e = tid; e < BB*NN*KD; e += 256) {
        int k2 = e & 63;
        float v = (g_kraw[e] - sm[k2]) * si[k2] * sg[k2] + sbt[k2];
        g_knorm[e] = v;
        if (write_pk) pk_out[e] = v;
    }
}

// ---------------- bmm (FFMA2, 2 px/thread) + stats ----------------
#define BMM_SMEM (NN*KD*8 + 2048)     // 61440 dup'd K + reduction
__global__ __launch_bounds__(256, 1)
void bmm_kernel(const float* __restrict__ mf, float* __restrict__ pm)
{
    extern __shared__ char bsm[];
    u64t* sK2 = (u64t*)bsm;                       // [n][k] duplicated
    float* rs = (float*)(bsm + NN*KD*8);
    float* rq = rs + 256;
    const int b = blockIdx.y;
    const int tid = threadIdx.x;
    const int v0 = blockIdx.x * 512 + tid;        // v1 = v0 + 256

    for (int i = tid; i < NN*KD; i += 256)
        sK2[i] = dup2(g_knorm[b*NN*KD + i]);
    __syncthreads();

    u64t mfv2[64];
    const float* mb = mf + (size_t)b*64*VV + v0;
    #pragma unroll
    for (int k = 0; k < 64; k++)
        mfv2[k] = pack2(mb[(size_t)k*VV], mb[(size_t)k*VV + 256]);

    u64t psum2 = 0, psq2 = 0;
    const u64t one2 = dup2(1.0f);
    float* po = pm + (size_t)b*NN*VV + v0;
    #pragma unroll 2
    for (int n = 0; n < NN; n++) {
        const ulonglong2* kp = (const ulonglong2*)(sK2 + n*64);
        u64t a2 = 0;
        #pragma unroll
        for (int kk = 0; kk < 32; kk++) {
            ulonglong2 kv = kp[kk];
            a2 = fma2(kv.x, mfv2[2*kk],     a2);
            a2 = fma2(kv.y, mfv2[2*kk + 1], a2);
        }
        float2 av = unpack2(a2);
        po[(size_t)n*VV]       = av.x;
        po[(size_t)n*VV + 256] = av.y;
        psum2 = fma2(a2, one2, psum2);
        psq2  = fma2(a2, a2, psq2);
    }
    float2 su = unpack2(psum2);
    float2 qu = unpack2(psq2);
    rs[tid] = su.x + su.y; rq[tid] = qu.x + qu.y;
    __syncthreads();
    for (int s = 128; s > 0; s >>= 1) {
        if (tid < s) { rs[tid] += rs[tid+s]; rq[tid] += rq[tid+s]; }
        __syncthreads();
    }
    if (tid == 0) {
        atomicAdd(&g_psum, (double)rs[0]);
        atomicAdd(&g_psumsq, (double)rq[0]);
    }
}

// ---------------- global BN over pred_masks ----------------
__global__ void norm_masks_kernel(float* __restrict__ pm,
                                  const float* __restrict__ gam,
                                  const float* __restrict__ bet)
{
    const double N = (double)PM_ELEMS;
    double mean = g_psum / N;
    double var = g_psumsq / N - mean*mean;
    float inv = (float)(1.0 / sqrt(var + (double)EPSV));
    float g = gam[0] * inv;
    float m = (float)mean;
    float be = bet[0];
    float4* p = (float4*)pm;
    const int n4 = PM_ELEMS / 4;
    for (int i = blockIdx.x*blockDim.x + threadIdx.x; i < n4; i += gridDim.x*blockDim.x) {
        float4 v = p[i];
        v.x = (v.x - m)*g + be;
        v.y = (v.y - m)*g + be;
        v.z = (v.z - m)*g + be;
        v.w = (v.w - m)*g + be;
        p[i] = v;
    }
}

// ---------------- launch ----------------
extern "C" void kernel_launch(void* const* d_in, const int* in_sizes, int n_in,
                              void* d_out, int out_size)
{
    const float* features      = (const float*)d_in[0];
    const float* mask_features = (const float*)d_in[1];
    const float* conv_w        = (const float*)d_in[2];
    const float* conv_b        = (const float*)d_in[3];
    const float* embed         = (const float*)d_in[4];
    const float* mk_w          = (const float*)d_in[5];
    const float* mk_b          = (const float*)d_in[6];
    const float* nk_gamma      = (const float*)d_in[7];
    const float* nk_beta       = (const float*)d_in[8];
    const float* nl_gamma      = (const float*)d_in[9];
    const float* nl_beta       = (const float*)d_in[10];
    const int*   init_masks    = (const int*)d_in[11];
    float* out = (float*)d_out;

    float *bufA = nullptr, *bufB = nullptr;
    uint4* wfrag = nullptr;
    cudaGetSymbolAddress((void**)&bufA, g_bufA);
    cudaGetSymbolAddress((void**)&bufB, g_bufB);
    cudaGetSymbolAddress((void**)&wfrag, g_wfragLo);
    uint16_t* hA = (uint16_t*)bufA;
    uint16_t* hB = (uint16_t*)bufB;

    int full = (out_size >= OUT_FULL) ? 1 : 0;
    int masks_only = (!full && out_size >= PM_ELEMS) ? 1 : 0;

    float* xout  = full ? out : bufB;
    float* ifout = full ? (out + X_ELEMS) : out;
    float* pmout = full ? (out + X_ELEMS + IF_ELEMS) : (masks_only ? out : bufB);
    float* pkout = full ? (out + X_ELEMS + IF_ELEMS + PM_ELEMS) : out;

    static int attr_done = 0;
    if (!attr_done) {
        cudaFuncSetAttribute(conv_mma_kernel,
                             cudaFuncAttributeMaxDynamicSharedMemorySize, CONV_SMEM);
        cudaFuncSetAttribute(bmm_kernel,
                             cudaFuncAttributeMaxDynamicSharedMemorySize, BMM_SMEM);
        attr_done = 1;
    }

    init_zero_kernel<<<1, 256>>>();
    wfrag_kernel<<<72, 256>>>(conv_w);
    trans_kernel<<<2048, 256>>>(features, hB);

    conv_mma_kernel<<<GRIDC, 256, CONV_SMEM>>>(hB, hA,   conv_w + 0*36864, wfrag + 0*4608, conv_b + 0,   0);
    conv_mma_kernel<<<GRIDC, 256, CONV_SMEM>>>(hA, hB,   conv_w + 1*36864, wfrag + 1*4608, conv_b + 64,  0);
    conv_mma_kernel<<<GRIDC, 256, CONV_SMEM>>>(hB, hA,   conv_w + 2*36864, wfrag + 2*4608, conv_b + 128, 0);
    conv_mma_kernel<<<GRIDC, 256, CONV_SMEM>>>(hA, xout, conv_w + 3*36864, wfrag + 3*4608, conv_b + 192, 1);

    segsum_kernel<<<dim3(VV/VCH, BB), 256>>>(xout, init_masks);
    instfeat_kernel<<<BB, 256>>>(embed, mk_w, mk_b, ifout, full);
    bnk_kernel<<<1, 256>>>(nk_gamma, nk_beta, pkout, full);

    if (full || masks_only) {
        bmm_kernel<<<dim3(VV/512, BB), 256, BMM_SMEM>>>(mask_features, pmout);
        norm_masks_kernel<<<4096, 256>>>(pmout, nl_gamma, nl_beta);
    }
}